// round 6
// baseline (speedup 1.0000x reference)
#include <cuda_runtime.h>
#include <math.h>
#include <math_constants.h>

#define B_SZ   2
#define S_LEN  2048
#define D_MOD  1024
#define NH     16
#define DK     64
#define M_TOT  (B_SZ * S_LEN)   // 4096

// Scratch (allocation-free rule: __device__ globals)
__device__ float g_X [M_TOT * D_MOD];   // x, tf32-rounded + k-permuted
__device__ float g_Wq[D_MOD * D_MOD];
__device__ float g_Wk[D_MOD * D_MOD];
__device__ float g_Wv[D_MOD * D_MOD];
__device__ float g_Wo[D_MOD * D_MOD];
__device__ float g_Q [M_TOT * D_MOD];   // rounded, col-permuted
__device__ float g_K [M_TOT * D_MOD];   // rounded, col-permuted
__device__ float g_VT[M_TOT * D_MOD];   // V transposed [b,h,d',s'], rounded
__device__ float g_AO[M_TOT * D_MOD];   // attention out, rounded, k-permuted
__device__ float g_freq[512];           // RoPE inv freqs per even col

__device__ __forceinline__ unsigned f2tf(float f) {
    unsigned u;
    asm("cvt.rna.tf32.f32 %0, %1;" : "=r"(u) : "f"(f));
    return u;
}
__device__ __forceinline__ float rtf(float f) { return __uint_as_float(f2tf(f)); }

__device__ __forceinline__ void mma8(float* d, const unsigned* a, const unsigned* b) {
    asm volatile(
        "mma.sync.aligned.m16n8k8.row.col.f32.tf32.tf32.f32 "
        "{%0,%1,%2,%3}, {%4,%5,%6,%7}, {%8,%9}, {%0,%1,%2,%3};\n"
        : "+f"(d[0]), "+f"(d[1]), "+f"(d[2]), "+f"(d[3])
        : "r"(a[0]), "r"(a[1]), "r"(a[2]), "r"(a[3]), "r"(b[0]), "r"(b[1]));
}

__device__ __forceinline__ void cp16(float* smem, const float* gmem) {
    unsigned s = (unsigned)__cvta_generic_to_shared(smem);
    asm volatile("cp.async.cg.shared.global [%0], [%1], 16;" :: "r"(s), "l"(gmem));
}
#define CP_COMMIT() asm volatile("cp.async.commit_group;")
#define CP_WAIT0()  asm volatile("cp.async.wait_group 0;")

// ============================================================================
// Pre-round + k-permute: tf32 RNA rounding; every 8-k group reordered to
// [k0,k4,k1,k5,k2,k6,k3,k7] so fragment pairs (c, c+4) sit adjacent (LDS.64).
// Also fills the RoPE freq table.
// ============================================================================
__global__ __launch_bounds__(256)
void preround(const float* __restrict__ x,
              const float* __restrict__ wq, const float* __restrict__ wk,
              const float* __restrict__ wv, const float* __restrict__ wo)
{
    if (blockIdx.x == 0 && threadIdx.x < 256) {
        #pragma unroll
        for (int q = 0; q < 2; q++) {
            int j = threadIdx.x + q * 256;
            g_freq[j] = (float)exp2((double)(2 * j) * (-13.287712379549449 / 1024.0));
        }
    }
    int gidx = blockIdx.x * blockDim.x + threadIdx.x;   // 8-float group id
    const float* src; float* dst; int off;
    if (gidx < 524288) { src = x; dst = g_X; off = gidx; }
    else {
        int t = gidx - 524288; int w = t >> 17; off = t & 131071;
        src = (w == 0) ? wq : (w == 1) ? wk : (w == 2) ? wv : wo;
        dst = (w == 0) ? g_Wq : (w == 1) ? g_Wk : (w == 2) ? g_Wv : g_Wo;
    }
    float4 a = ((const float4*)src)[off * 2];       // k0..k3
    float4 b = ((const float4*)src)[off * 2 + 1];   // k4..k7
    float4 o1 = make_float4(rtf(a.x), rtf(b.x), rtf(a.y), rtf(b.y));
    float4 o2 = make_float4(rtf(a.z), rtf(b.z), rtf(a.w), rtf(b.w));
    ((float4*)dst)[off * 2]     = o1;
    ((float4*)dst)[off * 2 + 1] = o2;
}

// ============================================================================
// TF32 GEMM: C = A @ W^T, pre-rounded & k-permuted inputs (no cvt in loop).
// CTA tile 128x256, K-step 32; 8 warps (2m x 4n), warp tile 64x64
// (4 mt x 8 nt of m16n8k8). cp.async double-buffered, LDS.64 fragments.
// mode 0 (QKV): z<2 -> RoPE+round+col-permute; z==2 -> V transpose store.
// mode 1: plain output (final projection).
// ============================================================================
#define SROW 36
#define GSTG (128 * SROW + 256 * SROW)        // 13824 floats per stage
#define GEMM_SMEM_BYTES (2 * GSTG * 4)        // 110592

__global__ __launch_bounds__(256)
void gemm_tf32(const float* __restrict__ A,
               const float* __restrict__ W0, const float* __restrict__ W1,
               const float* __restrict__ W2,
               float* __restrict__ C0, float* __restrict__ C1, float* __restrict__ C2,
               const int* __restrict__ tokpos, int mode)
{
    const float* W = W0; float* C = C0;
    if (blockIdx.z == 1) { W = W1; C = C1; }
    else if (blockIdx.z == 2) { W = W2; C = C2; }

    extern __shared__ __align__(16) float sm_g[];

    const int tid  = threadIdx.x;
    const int lane = tid & 31;
    const int warp = tid >> 5;
    const int wm = warp >> 2;   // 0..1
    const int wn = warp & 3;    // 0..3
    const int g = lane >> 2;    // 0..7
    const int c = lane & 3;     // 0..3
    const int m0 = blockIdx.y * 128;
    const int n0 = blockIdx.x * 256;

    const int crow = tid >> 3;            // 0..31
    const int cc4  = (tid & 7) << 2;      // 0..28

    float acc[4][8][4];
    #pragma unroll
    for (int i = 0; i < 4; i++)
        #pragma unroll
        for (int j = 0; j < 8; j++)
            #pragma unroll
            for (int r = 0; r < 4; r++) acc[i][j][r] = 0.f;

    // prologue: stage 0
    {
        float* Xs = sm_g;
        float* Ws = sm_g + 128 * SROW;
        #pragma unroll
        for (int p = 0; p < 4; p++) {
            int row = crow + p * 32;
            cp16(&Xs[row * SROW + cc4], A + (size_t)(m0 + row) * D_MOD + cc4);
        }
        #pragma unroll
        for (int p = 0; p < 8; p++) {
            int row = crow + p * 32;
            cp16(&Ws[row * SROW + cc4], W + (size_t)(n0 + row) * D_MOD + cc4);
        }
        CP_COMMIT();
    }

    const int NIT = D_MOD / 32;
    for (int it = 0; it < NIT; it++) {
        CP_WAIT0();
        __syncthreads();
        if (it + 1 < NIT) {
            int k0 = (it + 1) * 32;
            float* Xs = sm_g + ((it + 1) & 1) * GSTG;
            float* Ws = Xs + 128 * SROW;
            #pragma unroll
            for (int p = 0; p < 4; p++) {
                int row = crow + p * 32;
                cp16(&Xs[row * SROW + cc4], A + (size_t)(m0 + row) * D_MOD + k0 + cc4);
            }
            #pragma unroll
            for (int p = 0; p < 8; p++) {
                int row = crow + p * 32;
                cp16(&Ws[row * SROW + cc4], W + (size_t)(n0 + row) * D_MOD + k0 + cc4);
            }
            CP_COMMIT();
        }

        const float* Xs = sm_g + (it & 1) * GSTG;
        const float* Ws = Xs + 128 * SROW;

        #pragma unroll
        for (int ks = 0; ks < 4; ks++) {
            unsigned a[4][4], b[8][2];
            #pragma unroll
            for (int mt = 0; mt < 4; mt++) {
                int rb = wm * 64 + mt * 16;
                float2 v0 = *(const float2*)&Xs[(rb + g    ) * SROW + ks * 8 + 2 * c];
                float2 v1 = *(const float2*)&Xs[(rb + g + 8) * SROW + ks * 8 + 2 * c];
                a[mt][0] = __float_as_uint(v0.x);
                a[mt][1] = __float_as_uint(v1.x);
                a[mt][2] = __float_as_uint(v0.y);
                a[mt][3] = __float_as_uint(v1.y);
            }
            #pragma unroll
            for (int nt = 0; nt < 8; nt++) {
                float2 vb = *(const float2*)&Ws[(wn * 64 + nt * 8 + g) * SROW + ks * 8 + 2 * c];
                b[nt][0] = __float_as_uint(vb.x);
                b[nt][1] = __float_as_uint(vb.y);
            }
            #pragma unroll
            for (int mt = 0; mt < 4; mt++)
                #pragma unroll
                for (int nt = 0; nt < 8; nt++)
                    mma8(acc[mt][nt], a[mt], b[nt]);
        }
    }
    __syncthreads();

    // in-group permuted position of col offset 2c: (0,4,1,5 for c=0..3)
    const int qoff = ((2 * c) & 3) * 2 + (c >> 1);

    #pragma unroll
    for (int mt = 0; mt < 4; mt++) {
        int r0 = m0 + wm * 64 + mt * 16 + g;
        int r1 = r0 + 8;
        if (mode == 1) {
            #pragma unroll
            for (int nt = 0; nt < 8; nt++) {
                int col = n0 + wn * 64 + nt * 8 + c * 2;
                *(float2*)(C + (size_t)r0 * D_MOD + col) = make_float2(acc[mt][nt][0], acc[mt][nt][1]);
                *(float2*)(C + (size_t)r1 * D_MOD + col) = make_float2(acc[mt][nt][2], acc[mt][nt][3]);
            }
        } else if (blockIdx.z < 2) {
            // RoPE (true cols) + round + permuted store
            int p0 = tokpos[r0], p1 = tokpos[r1];
            float pf0 = (float)p0, pf1 = (float)p1;
            #pragma unroll
            for (int nt = 0; nt < 8; nt++) {
                int colgrp = n0 + wn * 64 + nt * 8;
                float x00 = acc[mt][nt][0], x01 = acc[mt][nt][1];
                float x10 = acc[mt][nt][2], x11 = acc[mt][nt][3];
                float freq = g_freq[(colgrp >> 1) + c];
                float s0, cs0, s1, cs1;
                sincosf(pf0 * freq, &s0, &cs0);
                sincosf(pf1 * freq, &s1, &cs1);
                float y00 = x00 * cs0 - x01 * s0, y01 = x00 * s0 + x01 * cs0;
                float y10 = x10 * cs1 - x11 * s1, y11 = x10 * s1 + x11 * cs1;
                C[(size_t)r0 * D_MOD + colgrp + qoff    ] = rtf(y00);
                C[(size_t)r0 * D_MOD + colgrp + qoff + 2] = rtf(y01);
                C[(size_t)r1 * D_MOD + colgrp + qoff    ] = rtf(y10);
                C[(size_t)r1 * D_MOD + colgrp + qoff + 2] = rtf(y11);
            }
        } else {
            // V: transposed store  g_VT[((b*16+h)*64 + d')*2048 + s']
            int bb = r0 >> 11;
            int s0i = r0 & 2047;
            int sq = (s0i & ~7) | (((s0i & 3) << 1) | ((s0i >> 2) & 1));
            #pragma unroll
            for (int nt = 0; nt < 8; nt++) {
                int colgrp = n0 + wn * 64 + nt * 8;
                int n = colgrp + 2 * c;
                int h = n >> 6, d = n & 63;
                int dq = (d & ~7) + qoff;
                size_t o = ((size_t)((bb << 4) | h) * 64 + dq) * 2048 + sq;
                C[o           ] = rtf(acc[mt][nt][0]);
                C[o + 4096    ] = rtf(acc[mt][nt][1]);   // d'+2
                C[o + 8       ] = rtf(acc[mt][nt][2]);   // s'+8 (row r1)
                C[o + 4096 + 8] = rtf(acc[mt][nt][3]);
            }
        }
    }
}

// ============================================================================
// Fused causal flash attention, 256 threads (8 warps), 128 queries per CTA.
// Pre-rounded, k-permuted Q/K; V transposed. Q fragments hoisted to regs;
// K/V^T cp.async double-buffered; k-tiles of 64. grid = (16, 32).
// ============================================================================
#define KSTR 72
#define FS_Q 0                            // 128x72 (reused as P after hoist)
#define FS_K 9216                         // + stage*4608
#define FS_V (9216 + 2*4608)              // 18432, + stage*4608
#define FLASH_SMEM_BYTES ((9216 + 4*4608) * 4)   // 110592

__global__ __launch_bounds__(256, 2)
void flash_attn()
{
    extern __shared__ __align__(16) float sm[];
    const int tid  = threadIdx.x;
    const int lane = tid & 31;
    const int warp = tid >> 5;   // 0..7
    const int g = lane >> 2;
    const int c = lane & 3;
    const int qt = (S_LEN / 128 - 1) - blockIdx.x;   // heavy tiles first
    const int bh = blockIdx.y;
    const int b = bh >> 4, h = bh & 15;

    const float* Qg  = g_Q  + ((size_t)(b * S_LEN + qt * 128)) * D_MOD + h * 64;
    const float* Kg  = g_K  + ((size_t)(b * S_LEN)) * D_MOD + h * 64;
    const float* VTg = g_VT + ((size_t)((b * 16 + h) * 64)) * 2048;

    const int crow = tid >> 4;          // 0..15
    const int cc4  = (tid & 15) << 2;   // 0..60

    // prologue: cp.async K/V^T stage 0 (kt = 0)
    #pragma unroll
    for (int p = 0; p < 4; p++) {
        int row = crow + p * 16;
        cp16(&sm[FS_K + row * KSTR + cc4], Kg  + (size_t)row * D_MOD + cc4);
        cp16(&sm[FS_V + row * KSTR + cc4], VTg + (size_t)row * 2048 + cc4);
    }
    CP_COMMIT();

    // Q tile load (scale by 1/8, exact) into FS_Q (128 rows)
    #pragma unroll
    for (int p = 0; p < 8; p++) {
        int row = crow + p * 16;
        float4 v = *(const float4*)(Qg + (size_t)row * D_MOD + cc4);
        v.x *= 0.125f; v.y *= 0.125f; v.z *= 0.125f; v.w *= 0.125f;
        *(float4*)(&sm[FS_Q + row * KSTR + cc4]) = v;
    }
    __syncthreads();

    // hoist Q fragments (32 regs); FS_Q becomes P after first loop sync
    const int qrow0 = warp * 16 + g;    // 0..127
    const int qrow1 = qrow0 + 8;
    unsigned qa[8][4];
    #pragma unroll
    for (int ks = 0; ks < 8; ks++) {
        float2 v0 = *(const float2*)&sm[FS_Q + qrow0 * KSTR + ks * 8 + 2 * c];
        float2 v1 = *(const float2*)&sm[FS_Q + qrow1 * KSTR + ks * 8 + 2 * c];
        qa[ks][0] = __float_as_uint(v0.x);
        qa[ks][1] = __float_as_uint(v1.x);
        qa[ks][2] = __float_as_uint(v0.y);
        qa[ks][3] = __float_as_uint(v1.y);
    }

    float m0f = -CUDART_INF_F, m1f = -CUDART_INF_F;
    float l0 = 0.f, l1 = 0.f;
    float o[8][4];
    #pragma unroll
    for (int dt = 0; dt < 8; dt++)
        #pragma unroll
        for (int r = 0; r < 4; r++) o[dt][r] = 0.f;

    const int qoff   = ((2 * c) & 3) * 2 + (c >> 1);
    const int gq0    = qt * 128 + qrow0;         // global query rows
    const int gq1    = gq0 + 8;
    const int wqmin  = qt * 128 + warp * 16;     // warp's min query
    const int wqmax  = wqmin + 15;
    const int NKT    = 2 * qt + 2;

    for (int kt = 0; kt < NKT; kt++) {
        CP_WAIT0();
        __syncthreads();
        if (kt + 1 < NKT) {
            int st = (kt + 1) & 1;
            #pragma unroll
            for (int p = 0; p < 4; p++) {
                int row = crow + p * 16;
                cp16(&sm[FS_K + st * 4608 + row * KSTR + cc4],
                     Kg + (size_t)((kt + 1) * 64 + row) * D_MOD + cc4);
                cp16(&sm[FS_V + st * 4608 + row * KSTR + cc4],
                     VTg + (size_t)row * 2048 + (kt + 1) * 64 + cc4);
            }
            CP_COMMIT();
        }
        if (kt * 64 > wqmax) continue;   // tile fully masked for this warp

        const float* Ks = sm + FS_K + (kt & 1) * 4608;
        const float* Vs = sm + FS_V + (kt & 1) * 4608;

        // S = Q @ K^T
        float sacc[8][4];
        #pragma unroll
        for (int nt = 0; nt < 8; nt++)
            #pragma unroll
            for (int r = 0; r < 4; r++) sacc[nt][r] = 0.f;

        #pragma unroll
        for (int ks = 0; ks < 8; ks++) {
            #pragma unroll
            for (int nt = 0; nt < 8; nt++) {
                float2 kb = *(const float2*)&Ks[(nt * 8 + g) * KSTR + ks * 8 + 2 * c];
                unsigned bf[2] = { __float_as_uint(kb.x), __float_as_uint(kb.y) };
                mma8(sacc[nt], qa[ks], bf);
            }
        }

        // causal mask (global indices)
        if (kt * 64 + 63 > wqmin) {
            #pragma unroll
            for (int nt = 0; nt < 8; nt++) {
                int gk0 = kt * 64 + nt * 8 + c * 2, gk1 = gk0 + 1;
                if (gk0 > gq0) sacc[nt][0] = -CUDART_INF_F;
                if (gk1 > gq0) sacc[nt][1] = -CUDART_INF_F;
                if (gk0 > gq1) sacc[nt][2] = -CUDART_INF_F;
                if (gk1 > gq1) sacc[nt][3] = -CUDART_INF_F;
            }
        }

        // online softmax
        float r0 = -CUDART_INF_F, r1 = -CUDART_INF_F;
        #pragma unroll
        for (int nt = 0; nt < 8; nt++) {
            r0 = fmaxf(r0, fmaxf(sacc[nt][0], sacc[nt][1]));
            r1 = fmaxf(r1, fmaxf(sacc[nt][2], sacc[nt][3]));
        }
        r0 = fmaxf(r0, __shfl_xor_sync(0xffffffffu, r0, 1));
        r0 = fmaxf(r0, __shfl_xor_sync(0xffffffffu, r0, 2));
        r1 = fmaxf(r1, __shfl_xor_sync(0xffffffffu, r1, 1));
        r1 = fmaxf(r1, __shfl_xor_sync(0xffffffffu, r1, 2));
        float mn0 = fmaxf(m0f, r0), mn1 = fmaxf(m1f, r1);
        float al0 = __expf(m0f - mn0), al1 = __expf(m1f - mn1);
        m0f = mn0; m1f = mn1;

        float rs0 = 0.f, rs1 = 0.f;
        #pragma unroll
        for (int nt = 0; nt < 8; nt++) {
            float p00 = __expf(sacc[nt][0] - mn0);
            float p01 = __expf(sacc[nt][1] - mn0);
            float p10 = __expf(sacc[nt][2] - mn1);
            float p11 = __expf(sacc[nt][3] - mn1);
            rs0 += p00 + p01; rs1 += p10 + p11;
            // P stored at key-permuted positions (matches V^T col permutation)
            int pb = nt * 8 + qoff;
            sm[FS_Q + qrow0 * KSTR + pb    ] = rtf(p00);
            sm[FS_Q + qrow0 * KSTR + pb + 2] = rtf(p01);
            sm[FS_Q + qrow1 * KSTR + pb    ] = rtf(p10);
            sm[FS_Q + qrow1 * KSTR + pb + 2] = rtf(p11);
        }
        l0 = l0 * al0 + rs0;
        l1 = l1 * al1 + rs1;
        #pragma unroll
        for (int dt = 0; dt < 8; dt++) {
            o[dt][0] *= al0; o[dt][1] *= al0;
            o[dt][2] *= al1; o[dt][3] *= al1;
        }
        __syncwarp();

        // O += P @ V  (V^T rows = dk, cols = keys; both via LDS.64)
        #pragma unroll
        for (int ks = 0; ks < 8; ks++) {
            float2 pa0 = *(const float2*)&sm[FS_Q + qrow0 * KSTR + ks * 8 + 2 * c];
            float2 pa1 = *(const float2*)&sm[FS_Q + qrow1 * KSTR + ks * 8 + 2 * c];
            unsigned a[4] = { __float_as_uint(pa0.x), __float_as_uint(pa1.x),
                              __float_as_uint(pa0.y), __float_as_uint(pa1.y) };
            #pragma unroll
            for (int dt = 0; dt < 8; dt++) {
                float2 vb = *(const float2*)&Vs[(dt * 8 + g) * KSTR + ks * 8 + 2 * c];
                unsigned bf[2] = { __float_as_uint(vb.x), __float_as_uint(vb.y) };
                mma8(o[dt], a, bf);
            }
        }
        __syncwarp();   // P reads done before next iter's P writes
    }

    l0 += __shfl_xor_sync(0xffffffffu, l0, 1);
    l0 += __shfl_xor_sync(0xffffffffu, l0, 2);
    l1 += __shfl_xor_sync(0xffffffffu, l1, 1);
    l1 += __shfl_xor_sync(0xffffffffu, l1, 2);
    float inv0 = 1.f / l0, inv1 = 1.f / l1;

    float* Og = g_AO + ((size_t)(b * S_LEN + qt * 128)) * D_MOD + h * 64;
    #pragma unroll
    for (int dt = 0; dt < 8; dt++) {
        int colb = dt * 8 + c * 2;
        *(float2*)(Og + (size_t)qrow0 * D_MOD + colb) =
            make_float2(rtf(o[dt][0] * inv0), rtf(o[dt][1] * inv0));
        *(float2*)(Og + (size_t)qrow1 * D_MOD + colb) =
            make_float2(rtf(o[dt][2] * inv1), rtf(o[dt][3] * inv1));
    }
}

// ============================================================================
extern "C" void kernel_launch(void* const* d_in, const int* in_sizes, int n_in,
                              void* d_out, int out_size)
{
    (void)in_sizes; (void)n_in; (void)out_size;
    const float* x  = (const float*)d_in[0];
    const int*   tp = (const int*)d_in[1];
    const float* wq = (const float*)d_in[2];
    const float* wk = (const float*)d_in[3];
    const float* wv = (const float*)d_in[4];
    const float* wo = (const float*)d_in[5];
    float* out = (float*)d_out;

    float *xptr, *wqp, *wkp, *wvp, *wop, *qptr, *kptr, *vtptr, *aoptr;
    cudaGetSymbolAddress((void**)&xptr,  g_X);
    cudaGetSymbolAddress((void**)&wqp,   g_Wq);
    cudaGetSymbolAddress((void**)&wkp,   g_Wk);
    cudaGetSymbolAddress((void**)&wvp,   g_Wv);
    cudaGetSymbolAddress((void**)&wop,   g_Wo);
    cudaGetSymbolAddress((void**)&qptr,  g_Q);
    cudaGetSymbolAddress((void**)&kptr,  g_K);
    cudaGetSymbolAddress((void**)&vtptr, g_VT);
    cudaGetSymbolAddress((void**)&aoptr, g_AO);

    cudaFuncSetAttribute(gemm_tf32, cudaFuncAttributeMaxDynamicSharedMemorySize,
                         GEMM_SMEM_BYTES);
    cudaFuncSetAttribute(flash_attn, cudaFuncAttributeMaxDynamicSharedMemorySize,
                         FLASH_SMEM_BYTES);

    // 0) round inputs to tf32 + k-permute + freq table
    preround<<<4096, 256>>>(x, wq, wk, wv, wo);

    // 1) Q/K/V projections (+ fused RoPE on Q,K; V stored transposed)
    dim3 gq(D_MOD / 256, M_TOT / 128, 3);
    gemm_tf32<<<gq, 256, GEMM_SMEM_BYTES>>>(xptr, wqp, wkp, wvp,
                                            qptr, kptr, vtptr, tp, 0);

    // 2) fused causal attention
    flash_attn<<<dim3(S_LEN / 128, B_SZ * NH), 256, FLASH_SMEM_BYTES>>>();

    // 3) output projection (plain epilogue)
    dim3 go(D_MOD / 256, M_TOT / 128, 1);
    gemm_tf32<<<go, 256, GEMM_SMEM_BYTES>>>(aoptr, wop, wop, wop,
                                            out, out, out, nullptr, 1);
}

// round 7
// speedup vs baseline: 1.0770x; 1.0770x over previous
#include <cuda_runtime.h>
#include <math.h>
#include <math_constants.h>

#define B_SZ   2
#define S_LEN  2048
#define D_MOD  1024
#define NH     16
#define DK     64
#define M_TOT  (B_SZ * S_LEN)   // 4096

// Scratch (allocation-free rule: __device__ globals)
__device__ float g_X [M_TOT * D_MOD];   // x, tf32-rounded + k-permuted
__device__ float g_Wq[D_MOD * D_MOD];
__device__ float g_Wk[D_MOD * D_MOD];
__device__ float g_Wv[D_MOD * D_MOD];
__device__ float g_Wo[D_MOD * D_MOD];
__device__ float g_Q [M_TOT * D_MOD];   // rounded, col-permuted
__device__ float g_K [M_TOT * D_MOD];   // rounded, col-permuted
__device__ float g_VT[M_TOT * D_MOD];   // V transposed [b,h,d',s'], rounded
__device__ float g_AO[M_TOT * D_MOD];   // attention out, rounded, k-permuted
__device__ float g_freq[512];           // RoPE inv freqs per even col

__device__ __forceinline__ unsigned f2tf(float f) {
    unsigned u;
    asm("cvt.rna.tf32.f32 %0, %1;" : "=r"(u) : "f"(f));
    return u;
}
__device__ __forceinline__ float rtf(float f) { return __uint_as_float(f2tf(f)); }

__device__ __forceinline__ void mma8(float* d, const unsigned* a, const unsigned* b) {
    asm volatile(
        "mma.sync.aligned.m16n8k8.row.col.f32.tf32.tf32.f32 "
        "{%0,%1,%2,%3}, {%4,%5,%6,%7}, {%8,%9}, {%0,%1,%2,%3};\n"
        : "+f"(d[0]), "+f"(d[1]), "+f"(d[2]), "+f"(d[3])
        : "r"(a[0]), "r"(a[1]), "r"(a[2]), "r"(a[3]), "r"(b[0]), "r"(b[1]));
}

__device__ __forceinline__ void cp16(float* smem, const float* gmem) {
    unsigned s = (unsigned)__cvta_generic_to_shared(smem);
    asm volatile("cp.async.cg.shared.global [%0], [%1], 16;" :: "r"(s), "l"(gmem));
}
#define CP_COMMIT() asm volatile("cp.async.commit_group;")
#define CP_WAIT0()  asm volatile("cp.async.wait_group 0;")
#define CP_WAIT1()  asm volatile("cp.async.wait_group 1;")

// ============================================================================
// Pre-round + k-permute: tf32 RNA rounding; every 8-k group reordered to
// [k0,k4,k1,k5,k2,k6,k3,k7] so fragment pairs (c, c+4) sit adjacent (LDS.64).
// Also fills the RoPE freq table.
// ============================================================================
__global__ __launch_bounds__(256)
void preround(const float* __restrict__ x,
              const float* __restrict__ wq, const float* __restrict__ wk,
              const float* __restrict__ wv, const float* __restrict__ wo)
{
    if (blockIdx.x == 0 && threadIdx.x < 256) {
        #pragma unroll
        for (int q = 0; q < 2; q++) {
            int j = threadIdx.x + q * 256;
            g_freq[j] = (float)exp2((double)(2 * j) * (-13.287712379549449 / 1024.0));
        }
    }
    int gidx = blockIdx.x * blockDim.x + threadIdx.x;   // 8-float group id
    const float* src; float* dst; int off;
    if (gidx < 524288) { src = x; dst = g_X; off = gidx; }
    else {
        int t = gidx - 524288; int w = t >> 17; off = t & 131071;
        src = (w == 0) ? wq : (w == 1) ? wk : (w == 2) ? wv : wo;
        dst = (w == 0) ? g_Wq : (w == 1) ? g_Wk : (w == 2) ? g_Wv : g_Wo;
    }
    float4 a = ((const float4*)src)[off * 2];       // k0..k3
    float4 b = ((const float4*)src)[off * 2 + 1];   // k4..k7
    float4 o1 = make_float4(rtf(a.x), rtf(b.x), rtf(a.y), rtf(b.y));
    float4 o2 = make_float4(rtf(a.z), rtf(b.z), rtf(a.w), rtf(b.w));
    ((float4*)dst)[off * 2]     = o1;
    ((float4*)dst)[off * 2 + 1] = o2;
}

// ============================================================================
// TF32 GEMM: C = A @ W^T, pre-rounded & k-permuted inputs (no cvt in loop).
// 128x128x32 tiles, 8 warps (2m x 4n), warp tile 64x32, LDS.64 fragments.
// 3-stage cp.async pipeline, wait_group 1 (copy gets 2 compute iters to land).
// mode 0 (QKV): z<2 -> RoPE+round+col-permute; z==2 -> V transpose store.
// mode 1: plain output (final projection).
// ============================================================================
#define SROW 36
#define GSTG (256 * SROW)                     // 9216 floats per stage (A+B)
#define GEMM_SMEM_BYTES (3 * GSTG * 4)        // 110592

__device__ __forceinline__ void g_copy(float* stg, const float* A, const float* W,
                                       int m0, int n0, int k0, int crow, int cc4)
{
    #pragma unroll
    for (int p = 0; p < 4; p++) {
        int row = crow + p * 32;
        cp16(&stg[row * SROW + cc4],
             A + (size_t)(m0 + row) * D_MOD + k0 + cc4);
        cp16(&stg[128 * SROW + row * SROW + cc4],
             W + (size_t)(n0 + row) * D_MOD + k0 + cc4);
    }
    CP_COMMIT();
}

__global__ __launch_bounds__(256, 2)
void gemm_tf32(const float* __restrict__ A,
               const float* __restrict__ W0, const float* __restrict__ W1,
               const float* __restrict__ W2,
               float* __restrict__ C0, float* __restrict__ C1, float* __restrict__ C2,
               const int* __restrict__ tokpos, int mode)
{
    const float* W = W0; float* C = C0;
    if (blockIdx.z == 1) { W = W1; C = C1; }
    else if (blockIdx.z == 2) { W = W2; C = C2; }

    extern __shared__ __align__(16) float sm_g[];

    const int tid  = threadIdx.x;
    const int lane = tid & 31;
    const int warp = tid >> 5;
    const int wm = warp >> 2;   // 0..1
    const int wn = warp & 3;    // 0..3
    const int g = lane >> 2;    // 0..7
    const int c = lane & 3;     // 0..3
    const int m0 = blockIdx.y * 128;
    const int n0 = blockIdx.x * 128;

    const int crow = tid >> 3;            // 0..31
    const int cc4  = (tid & 7) << 2;      // 0..28

    float acc[4][4][4];
    #pragma unroll
    for (int i = 0; i < 4; i++)
        #pragma unroll
        for (int j = 0; j < 4; j++)
            #pragma unroll
            for (int r = 0; r < 4; r++) acc[i][j][r] = 0.f;

    // prologue: stages 0, 1
    g_copy(sm_g,        A, W, m0, n0, 0,  crow, cc4);
    g_copy(sm_g + GSTG, A, W, m0, n0, 32, crow, cc4);

    const int NIT = D_MOD / 32;   // 32
    for (int it = 0; it < NIT; it++) {
        if (it == NIT - 1) { CP_WAIT0(); } else { CP_WAIT1(); }   // stage(it) ready
        __syncthreads();          // also: all warps done with stage(it-1)
        if (it + 2 < NIT)
            g_copy(sm_g + ((it + 2) % 3) * GSTG, A, W, m0, n0, (it + 2) * 32, crow, cc4);

        const float* Xs = sm_g + (it % 3) * GSTG;
        const float* Ws = Xs + 128 * SROW;

        #pragma unroll
        for (int ks = 0; ks < 4; ks++) {
            unsigned a[4][4], b[4][2];
            #pragma unroll
            for (int mt = 0; mt < 4; mt++) {
                int rb = wm * 64 + mt * 16;
                float2 v0 = *(const float2*)&Xs[(rb + g    ) * SROW + ks * 8 + 2 * c];
                float2 v1 = *(const float2*)&Xs[(rb + g + 8) * SROW + ks * 8 + 2 * c];
                a[mt][0] = __float_as_uint(v0.x);
                a[mt][1] = __float_as_uint(v1.x);
                a[mt][2] = __float_as_uint(v0.y);
                a[mt][3] = __float_as_uint(v1.y);
            }
            #pragma unroll
            for (int nt = 0; nt < 4; nt++) {
                float2 vb = *(const float2*)&Ws[(wn * 32 + nt * 8 + g) * SROW + ks * 8 + 2 * c];
                b[nt][0] = __float_as_uint(vb.x);
                b[nt][1] = __float_as_uint(vb.y);
            }
            #pragma unroll
            for (int mt = 0; mt < 4; mt++)
                #pragma unroll
                for (int nt = 0; nt < 4; nt++)
                    mma8(acc[mt][nt], a[mt], b[nt]);
        }
    }
    __syncthreads();

    // in-group permuted position of col offset 2c: (0,4,1,5 for c=0..3)
    const int qoff = ((2 * c) & 3) * 2 + (c >> 1);

    #pragma unroll
    for (int mt = 0; mt < 4; mt++) {
        int r0 = m0 + wm * 64 + mt * 16 + g;
        int r1 = r0 + 8;
        if (mode == 1) {
            #pragma unroll
            for (int nt = 0; nt < 4; nt++) {
                int col = n0 + wn * 32 + nt * 8 + c * 2;
                *(float2*)(C + (size_t)r0 * D_MOD + col) = make_float2(acc[mt][nt][0], acc[mt][nt][1]);
                *(float2*)(C + (size_t)r1 * D_MOD + col) = make_float2(acc[mt][nt][2], acc[mt][nt][3]);
            }
        } else if (blockIdx.z < 2) {
            // RoPE (true cols) + round + permuted store
            int p0 = tokpos[r0], p1 = tokpos[r1];
            float pf0 = (float)p0, pf1 = (float)p1;
            #pragma unroll
            for (int nt = 0; nt < 4; nt++) {
                int colgrp = n0 + wn * 32 + nt * 8;
                float x00 = acc[mt][nt][0], x01 = acc[mt][nt][1];
                float x10 = acc[mt][nt][2], x11 = acc[mt][nt][3];
                float freq = g_freq[(colgrp >> 1) + c];
                float s0, cs0, s1, cs1;
                sincosf(pf0 * freq, &s0, &cs0);
                sincosf(pf1 * freq, &s1, &cs1);
                float y00 = x00 * cs0 - x01 * s0, y01 = x00 * s0 + x01 * cs0;
                float y10 = x10 * cs1 - x11 * s1, y11 = x10 * s1 + x11 * cs1;
                C[(size_t)r0 * D_MOD + colgrp + qoff    ] = rtf(y00);
                C[(size_t)r0 * D_MOD + colgrp + qoff + 2] = rtf(y01);
                C[(size_t)r1 * D_MOD + colgrp + qoff    ] = rtf(y10);
                C[(size_t)r1 * D_MOD + colgrp + qoff + 2] = rtf(y11);
            }
        } else {
            // V: transposed store  g_VT[((b*16+h)*64 + d')*2048 + s']
            int bb = r0 >> 11;
            int s0i = r0 & 2047;
            int sq = (s0i & ~7) | (((s0i & 3) << 1) | ((s0i >> 2) & 1));
            #pragma unroll
            for (int nt = 0; nt < 4; nt++) {
                int colgrp = n0 + wn * 32 + nt * 8;
                int n = colgrp + 2 * c;
                int h = n >> 6, d = n & 63;
                int dq = (d & ~7) + qoff;
                size_t o = ((size_t)((bb << 4) | h) * 64 + dq) * 2048 + sq;
                C[o           ] = rtf(acc[mt][nt][0]);
                C[o + 4096    ] = rtf(acc[mt][nt][1]);   // d'+2
                C[o + 8       ] = rtf(acc[mt][nt][2]);   // s'+8 (row r1)
                C[o + 4096 + 8] = rtf(acc[mt][nt][3]);
            }
        }
    }
}

// ============================================================================
// Fused causal flash attention (round-4 config: 128 threads, 64 queries/CTA).
// Pre-rounded, k-permuted Q/K; V transposed. Q fragments hoisted to regs;
// K/V^T cp.async double-buffered. grid = (32, 32).
// ============================================================================
#define KSTR 72
#define FS_Q 0
#define FS_K 4608
#define FS_V (4608 + 2*4608)
#define FLASH_SMEM_BYTES (4608 * 5 * 4)

__global__ __launch_bounds__(128)
void flash_attn()
{
    extern __shared__ __align__(16) float sm[];
    const int tid  = threadIdx.x;
    const int lane = tid & 31;
    const int warp = tid >> 5;
    const int g = lane >> 2;
    const int c = lane & 3;
    const int qt = (S_LEN / 64 - 1) - blockIdx.x;   // heavy tiles first
    const int bh = blockIdx.y;
    const int b = bh >> 4, h = bh & 15;

    const float* Qg  = g_Q  + ((size_t)(b * S_LEN + qt * 64)) * D_MOD + h * 64;
    const float* Kg  = g_K  + ((size_t)(b * S_LEN)) * D_MOD + h * 64;
    const float* VTg = g_VT + ((size_t)((b * 16 + h) * 64)) * 2048;

    const int crow = tid >> 4;
    const int cc4  = (tid & 15) << 2;

    #pragma unroll
    for (int p = 0; p < 8; p++) {
        int row = crow + p * 8;
        cp16(&sm[FS_K + row * KSTR + cc4], Kg  + (size_t)row * D_MOD + cc4);
        cp16(&sm[FS_V + row * KSTR + cc4], VTg + (size_t)row * 2048 + cc4);
    }
    CP_COMMIT();

    #pragma unroll
    for (int p = 0; p < 8; p++) {
        int row = crow + p * 8;
        float4 v = *(const float4*)(Qg + (size_t)row * D_MOD + cc4);
        v.x *= 0.125f; v.y *= 0.125f; v.z *= 0.125f; v.w *= 0.125f;
        *(float4*)(&sm[FS_Q + row * KSTR + cc4]) = v;
    }
    __syncthreads();

    unsigned qa[8][4];
    #pragma unroll
    for (int ks = 0; ks < 8; ks++) {
        float2 v0 = *(const float2*)&sm[FS_Q + (warp * 16 + g    ) * KSTR + ks * 8 + 2 * c];
        float2 v1 = *(const float2*)&sm[FS_Q + (warp * 16 + g + 8) * KSTR + ks * 8 + 2 * c];
        qa[ks][0] = __float_as_uint(v0.x);
        qa[ks][1] = __float_as_uint(v1.x);
        qa[ks][2] = __float_as_uint(v0.y);
        qa[ks][3] = __float_as_uint(v1.y);
    }

    float m0f = -CUDART_INF_F, m1f = -CUDART_INF_F;
    float l0 = 0.f, l1 = 0.f;
    float o[8][4];
    #pragma unroll
    for (int dt = 0; dt < 8; dt++)
        #pragma unroll
        for (int r = 0; r < 4; r++) o[dt][r] = 0.f;

    const int qrow0 = warp * 16 + g;
    const int qrow1 = qrow0 + 8;
    const int qoff  = ((2 * c) & 3) * 2 + (c >> 1);

    for (int kt = 0; kt <= qt; kt++) {
        CP_WAIT0();
        __syncthreads();
        if (kt < qt) {
            int st = (kt + 1) & 1;
            #pragma unroll
            for (int p = 0; p < 8; p++) {
                int row = crow + p * 8;
                cp16(&sm[FS_K + st * 4608 + row * KSTR + cc4],
                     Kg + (size_t)((kt + 1) * 64 + row) * D_MOD + cc4);
                cp16(&sm[FS_V + st * 4608 + row * KSTR + cc4],
                     VTg + (size_t)row * 2048 + (kt + 1) * 64 + cc4);
            }
            CP_COMMIT();
        }
        const float* Ks = sm + FS_K + (kt & 1) * 4608;
        const float* Vs = sm + FS_V + (kt & 1) * 4608;

        float sacc[8][4];
        #pragma unroll
        for (int nt = 0; nt < 8; nt++)
            #pragma unroll
            for (int r = 0; r < 4; r++) sacc[nt][r] = 0.f;

        #pragma unroll
        for (int ks = 0; ks < 8; ks++) {
            #pragma unroll
            for (int nt = 0; nt < 8; nt++) {
                float2 kb = *(const float2*)&Ks[(nt * 8 + g) * KSTR + ks * 8 + 2 * c];
                unsigned bf[2] = { __float_as_uint(kb.x), __float_as_uint(kb.y) };
                mma8(sacc[nt], qa[ks], bf);
            }
        }

        if (kt == qt) {
            #pragma unroll
            for (int nt = 0; nt < 8; nt++) {
                int k0c = nt * 8 + c * 2, k1c = k0c + 1;
                if (k0c > qrow0) sacc[nt][0] = -CUDART_INF_F;
                if (k1c > qrow0) sacc[nt][1] = -CUDART_INF_F;
                if (k0c > qrow1) sacc[nt][2] = -CUDART_INF_F;
                if (k1c > qrow1) sacc[nt][3] = -CUDART_INF_F;
            }
        }

        float r0 = -CUDART_INF_F, r1 = -CUDART_INF_F;
        #pragma unroll
        for (int nt = 0; nt < 8; nt++) {
            r0 = fmaxf(r0, fmaxf(sacc[nt][0], sacc[nt][1]));
            r1 = fmaxf(r1, fmaxf(sacc[nt][2], sacc[nt][3]));
        }
        r0 = fmaxf(r0, __shfl_xor_sync(0xffffffffu, r0, 1));
        r0 = fmaxf(r0, __shfl_xor_sync(0xffffffffu, r0, 2));
        r1 = fmaxf(r1, __shfl_xor_sync(0xffffffffu, r1, 1));
        r1 = fmaxf(r1, __shfl_xor_sync(0xffffffffu, r1, 2));
        float mn0 = fmaxf(m0f, r0), mn1 = fmaxf(m1f, r1);
        float al0 = __expf(m0f - mn0), al1 = __expf(m1f - mn1);
        m0f = mn0; m1f = mn1;

        float rs0 = 0.f, rs1 = 0.f;
        #pragma unroll
        for (int nt = 0; nt < 8; nt++) {
            float p00 = __expf(sacc[nt][0] - mn0);
            float p01 = __expf(sacc[nt][1] - mn0);
            float p10 = __expf(sacc[nt][2] - mn1);
            float p11 = __expf(sacc[nt][3] - mn1);
            rs0 += p00 + p01; rs1 += p10 + p11;
            int pb = nt * 8 + qoff;
            sm[FS_Q + qrow0 * KSTR + pb    ] = rtf(p00);
            sm[FS_Q + qrow0 * KSTR + pb + 2] = rtf(p01);
            sm[FS_Q + qrow1 * KSTR + pb    ] = rtf(p10);
            sm[FS_Q + qrow1 * KSTR + pb + 2] = rtf(p11);
        }
        l0 = l0 * al0 + rs0;
        l1 = l1 * al1 + rs1;
        #pragma unroll
        for (int dt = 0; dt < 8; dt++) {
            o[dt][0] *= al0; o[dt][1] *= al0;
            o[dt][2] *= al1; o[dt][3] *= al1;
        }
        __syncwarp();

        #pragma unroll
        for (int ks = 0; ks < 8; ks++) {
            float2 pa0 = *(const float2*)&sm[FS_Q + qrow0 * KSTR + ks * 8 + 2 * c];
            float2 pa1 = *(const float2*)&sm[FS_Q + qrow1 * KSTR + ks * 8 + 2 * c];
            unsigned a[4] = { __float_as_uint(pa0.x), __float_as_uint(pa1.x),
                              __float_as_uint(pa0.y), __float_as_uint(pa1.y) };
            #pragma unroll
            for (int dt = 0; dt < 8; dt++) {
                float2 vb = *(const float2*)&Vs[(dt * 8 + g) * KSTR + ks * 8 + 2 * c];
                unsigned bf[2] = { __float_as_uint(vb.x), __float_as_uint(vb.y) };
                mma8(o[dt], a, bf);
            }
        }
        __syncwarp();
    }

    l0 += __shfl_xor_sync(0xffffffffu, l0, 1);
    l0 += __shfl_xor_sync(0xffffffffu, l0, 2);
    l1 += __shfl_xor_sync(0xffffffffu, l1, 1);
    l1 += __shfl_xor_sync(0xffffffffu, l1, 2);
    float inv0 = 1.f / l0, inv1 = 1.f / l1;

    float* Og = g_AO + ((size_t)(b * S_LEN + qt * 64)) * D_MOD + h * 64;
    #pragma unroll
    for (int dt = 0; dt < 8; dt++) {
        int colb = dt * 8 + c * 2;
        *(float2*)(Og + (size_t)qrow0 * D_MOD + colb) =
            make_float2(rtf(o[dt][0] * inv0), rtf(o[dt][1] * inv0));
        *(float2*)(Og + (size_t)qrow1 * D_MOD + colb) =
            make_float2(rtf(o[dt][2] * inv1), rtf(o[dt][3] * inv1));
    }
}

// ============================================================================
extern "C" void kernel_launch(void* const* d_in, const int* in_sizes, int n_in,
                              void* d_out, int out_size)
{
    (void)in_sizes; (void)n_in; (void)out_size;
    const float* x  = (const float*)d_in[0];
    const int*   tp = (const int*)d_in[1];
    const float* wq = (const float*)d_in[2];
    const float* wk = (const float*)d_in[3];
    const float* wv = (const float*)d_in[4];
    const float* wo = (const float*)d_in[5];
    float* out = (float*)d_out;

    float *xptr, *wqp, *wkp, *wvp, *wop, *qptr, *kptr, *vtptr, *aoptr;
    cudaGetSymbolAddress((void**)&xptr,  g_X);
    cudaGetSymbolAddress((void**)&wqp,   g_Wq);
    cudaGetSymbolAddress((void**)&wkp,   g_Wk);
    cudaGetSymbolAddress((void**)&wvp,   g_Wv);
    cudaGetSymbolAddress((void**)&wop,   g_Wo);
    cudaGetSymbolAddress((void**)&qptr,  g_Q);
    cudaGetSymbolAddress((void**)&kptr,  g_K);
    cudaGetSymbolAddress((void**)&vtptr, g_VT);
    cudaGetSymbolAddress((void**)&aoptr, g_AO);

    cudaFuncSetAttribute(gemm_tf32, cudaFuncAttributeMaxDynamicSharedMemorySize,
                         GEMM_SMEM_BYTES);
    cudaFuncSetAttribute(flash_attn, cudaFuncAttributeMaxDynamicSharedMemorySize,
                         FLASH_SMEM_BYTES);

    // 0) round inputs to tf32 + k-permute + freq table
    preround<<<4096, 256>>>(x, wq, wk, wv, wo);

    // 1) Q/K/V projections (+ fused RoPE on Q,K; V stored transposed)
    dim3 gq(D_MOD / 128, M_TOT / 128, 3);
    gemm_tf32<<<gq, 256, GEMM_SMEM_BYTES>>>(xptr, wqp, wkp, wvp,
                                            qptr, kptr, vtptr, tp, 0);

    // 2) fused causal attention
    flash_attn<<<dim3(S_LEN / 64, B_SZ * NH), 128, FLASH_SMEM_BYTES>>>();

    // 3) output projection (plain epilogue)
    dim3 go(D_MOD / 128, M_TOT / 128, 1);
    gemm_tf32<<<go, 256, GEMM_SMEM_BYTES>>>(aoptr, wop, wop, wop,
                                            out, out, out, nullptr, 1);
}

// round 8
// speedup vs baseline: 2.2584x; 2.0970x over previous
#include <cuda_runtime.h>
#include <cuda_fp16.h>
#include <math.h>
#include <math_constants.h>

#define B_SZ   2
#define S_LEN  2048
#define D_MOD  1024
#define NH     16
#define DK     64
#define M_TOT  (B_SZ * S_LEN)   // 4096

// Scratch (allocation-free rule: __device__ globals). All fp16, k-dim stored
// in per-16 interleaved order [k0,k1,k8,k9,k2,k3,k10,k11,k4,k5,k12,k13,k6,k7,k14,k15]
// so one LDS.64 yields an m16n8k16 fragment pair (2c,2c+1 | 2c+8,2c+9).
__device__ __half g_X [M_TOT * D_MOD];
__device__ __half g_Wq[D_MOD * D_MOD];
__device__ __half g_Wk[D_MOD * D_MOD];
__device__ __half g_Wv[D_MOD * D_MOD];
__device__ __half g_Wo[D_MOD * D_MOD];
__device__ __half g_Q [M_TOT * D_MOD];
__device__ __half g_K [M_TOT * D_MOD];
__device__ __half g_VT[M_TOT * D_MOD];   // V transposed [b,h,d,s_perm]
__device__ __half g_AO[M_TOT * D_MOD];   // attention out (perm-16 along d)
__device__ float  g_freq[512];           // RoPE inv freqs per even col

__device__ __forceinline__ unsigned h2u(__half2 v) { return *(unsigned*)&v; }

__device__ __forceinline__ void mma16(float* d,
                                      unsigned a0, unsigned a1, unsigned a2, unsigned a3,
                                      unsigned b0, unsigned b1) {
    asm volatile(
        "mma.sync.aligned.m16n8k16.row.col.f32.f16.f16.f32 "
        "{%0,%1,%2,%3}, {%4,%5,%6,%7}, {%8,%9}, {%0,%1,%2,%3};\n"
        : "+f"(d[0]), "+f"(d[1]), "+f"(d[2]), "+f"(d[3])
        : "r"(a0), "r"(a1), "r"(a2), "r"(a3), "r"(b0), "r"(b1));
}

__device__ __forceinline__ void cp16(void* smem, const void* gmem) {
    unsigned s = (unsigned)__cvta_generic_to_shared(smem);
    asm volatile("cp.async.cg.shared.global [%0], [%1], 16;" :: "r"(s), "l"(gmem));
}
#define CP_COMMIT() asm volatile("cp.async.commit_group;")
#define CP_WAIT0()  asm volatile("cp.async.wait_group 0;")

// position of key j (0..15) in the per-16 interleave
__device__ __forceinline__ int p16(int j) {
    return (j < 8) ? (4 * (j >> 1) + (j & 1)) : (4 * ((j - 8) >> 1) + 2 + (j & 1));
}

// ============================================================================
// Pre-round fp32 -> fp16 (rn) + per-16 k-interleave. Also fills freq table.
// One thread = one 16-float group. x: 262144 groups; each W: 65536.
// ============================================================================
__global__ __launch_bounds__(256)
void preround(const float* __restrict__ x,
              const float* __restrict__ wq, const float* __restrict__ wk,
              const float* __restrict__ wv, const float* __restrict__ wo)
{
    if (blockIdx.x == 0 && threadIdx.x < 256) {
        #pragma unroll
        for (int q = 0; q < 2; q++) {
            int j = threadIdx.x + q * 256;
            g_freq[j] = (float)exp2((double)(2 * j) * (-13.287712379549449 / 1024.0));
        }
    }
    int gidx = blockIdx.x * blockDim.x + threadIdx.x;
    const float* src; __half* dst; int off;
    if (gidx < 262144) { src = x; dst = g_X; off = gidx; }
    else {
        int t = gidx - 262144; int w = t >> 16; off = t & 65535;
        src = (w == 0) ? wq : (w == 1) ? wk : (w == 2) ? wv : wo;
        dst = (w == 0) ? g_Wq : (w == 1) ? g_Wk : (w == 2) ? g_Wv : g_Wo;
    }
    const float4* s4 = (const float4*)src + (size_t)off * 4;
    float4 f0 = s4[0], f1 = s4[1], f2 = s4[2], f3 = s4[3];
    // interleave: [0,1, 8,9, 2,3, 10,11, 4,5, 12,13, 6,7, 14,15]
    uint4 u0, u1;
    u0.x = h2u(__floats2half2_rn(f0.x, f0.y));   // 0,1
    u0.y = h2u(__floats2half2_rn(f2.x, f2.y));   // 8,9
    u0.z = h2u(__floats2half2_rn(f0.z, f0.w));   // 2,3
    u0.w = h2u(__floats2half2_rn(f2.z, f2.w));   // 10,11
    u1.x = h2u(__floats2half2_rn(f1.x, f1.y));   // 4,5
    u1.y = h2u(__floats2half2_rn(f3.x, f3.y));   // 12,13
    u1.z = h2u(__floats2half2_rn(f1.z, f1.w));   // 6,7
    u1.w = h2u(__floats2half2_rn(f3.z, f3.w));   // 14,15
    uint4* d4 = (uint4*)(dst + (size_t)off * 16);
    d4[0] = u0;
    d4[1] = u1;
}

// ============================================================================
// FP16 GEMM: C = A @ W^T. 128x128 CTA tile, K-stage 64 halves, 16 iters.
// 8 warps (2m x 4n), warp tile 64x32, m16n8k16, LDS.64 fragments.
// 2-stage cp.async (round-4 schedule). Row stride 80 halves (=160B, proven).
// mode 0: z<2 -> RoPE+half+perm16 (Q/K); z==2 -> V transpose store.
// mode 1: plain fp32 output.
// ============================================================================
#define SROWH 80
#define GSTGH (256 * SROWH)                    // 20480 halves per stage
#define GEMM_SMEM_BYTES (2 * GSTGH * 2)        // 81920

__global__ __launch_bounds__(256, 2)
void gemm_f16(const __half* __restrict__ A,
              const __half* __restrict__ W0, const __half* __restrict__ W1,
              const __half* __restrict__ W2,
              void* __restrict__ C0v, void* __restrict__ C1v, void* __restrict__ C2v,
              const int* __restrict__ tokpos, int mode)
{
    const __half* W = W0; void* Cv = C0v;
    if (blockIdx.z == 1) { W = W1; Cv = C1v; }
    else if (blockIdx.z == 2) { W = W2; Cv = C2v; }

    extern __shared__ __align__(16) __half smh[];

    const int tid  = threadIdx.x;
    const int lane = tid & 31;
    const int warp = tid >> 5;
    const int wm = warp >> 2;   // 0..1
    const int wn = warp & 3;    // 0..3
    const int g = lane >> 2;    // 0..7
    const int c = lane & 3;     // 0..3
    const int m0 = blockIdx.y * 128;
    const int n0 = blockIdx.x * 128;

    const int crow = tid >> 3;            // 0..31
    const int cc8  = (tid & 7) << 3;      // 0..56 (halves, 16B chunks)

    float acc[4][4][4];
    #pragma unroll
    for (int i = 0; i < 4; i++)
        #pragma unroll
        for (int j = 0; j < 4; j++)
            #pragma unroll
            for (int r = 0; r < 4; r++) acc[i][j][r] = 0.f;

    // prologue: stage 0 (K halves 0..63)
    {
        __half* Xs = smh;
        __half* Ws = smh + 128 * SROWH;
        #pragma unroll
        for (int p = 0; p < 4; p++) {
            int row = crow + p * 32;
            cp16(&Xs[row * SROWH + cc8], A + (size_t)(m0 + row) * D_MOD + cc8);
            cp16(&Ws[row * SROWH + cc8], W + (size_t)(n0 + row) * D_MOD + cc8);
        }
        CP_COMMIT();
    }

    const int NIT = D_MOD / 64;   // 16
    for (int it = 0; it < NIT; it++) {
        CP_WAIT0();
        __syncthreads();
        if (it + 1 < NIT) {
            int k0 = (it + 1) * 64;
            __half* Xs = smh + ((it + 1) & 1) * GSTGH;
            __half* Ws = Xs + 128 * SROWH;
            #pragma unroll
            for (int p = 0; p < 4; p++) {
                int row = crow + p * 32;
                cp16(&Xs[row * SROWH + cc8], A + (size_t)(m0 + row) * D_MOD + k0 + cc8);
                cp16(&Ws[row * SROWH + cc8], W + (size_t)(n0 + row) * D_MOD + k0 + cc8);
            }
            CP_COMMIT();
        }

        const __half* Xs = smh + (it & 1) * GSTGH;
        const __half* Ws = Xs + 128 * SROWH;

        #pragma unroll
        for (int ks = 0; ks < 4; ks++) {
            unsigned a[4][4], b[4][2];
            #pragma unroll
            for (int mt = 0; mt < 4; mt++) {
                int rb = wm * 64 + mt * 16;
                uint2 v0 = *(const uint2*)&Xs[(rb + g    ) * SROWH + ks * 16 + 4 * c];
                uint2 v1 = *(const uint2*)&Xs[(rb + g + 8) * SROWH + ks * 16 + 4 * c];
                a[mt][0] = v0.x; a[mt][1] = v1.x;
                a[mt][2] = v0.y; a[mt][3] = v1.y;
            }
            #pragma unroll
            for (int nt = 0; nt < 4; nt++) {
                uint2 vb = *(const uint2*)&Ws[(wn * 32 + nt * 8 + g) * SROWH + ks * 16 + 4 * c];
                b[nt][0] = vb.x; b[nt][1] = vb.y;
            }
            #pragma unroll
            for (int mt = 0; mt < 4; mt++)
                #pragma unroll
                for (int nt = 0; nt < 4; nt++)
                    mma16(acc[mt][nt], a[mt][0], a[mt][1], a[mt][2], a[mt][3],
                          b[nt][0], b[nt][1]);
        }
    }
    __syncthreads();

    #pragma unroll
    for (int mt = 0; mt < 4; mt++) {
        int r0 = m0 + wm * 64 + mt * 16 + g;
        int r1 = r0 + 8;
        if (mode == 1) {
            float* C = (float*)Cv;
            #pragma unroll
            for (int nt = 0; nt < 4; nt++) {
                int col = n0 + wn * 32 + nt * 8 + c * 2;
                *(float2*)(C + (size_t)r0 * D_MOD + col) = make_float2(acc[mt][nt][0], acc[mt][nt][1]);
                *(float2*)(C + (size_t)r1 * D_MOD + col) = make_float2(acc[mt][nt][2], acc[mt][nt][3]);
            }
        } else if (blockIdx.z < 2) {
            // Q/K: RoPE (natural col pairs) -> half -> perm16 store
            __half* C = (__half*)Cv;
            float pf0 = (float)tokpos[r0], pf1 = (float)tokpos[r1];
            #pragma unroll
            for (int nt = 0; nt < 4; nt++) {
                int colgrp = n0 + wn * 32 + nt * 8;
                float x00 = acc[mt][nt][0], x01 = acc[mt][nt][1];
                float x10 = acc[mt][nt][2], x11 = acc[mt][nt][3];
                float freq = g_freq[(colgrp >> 1) + c];
                float s0, cs0, s1, cs1;
                sincosf(pf0 * freq, &s0, &cs0);
                sincosf(pf1 * freq, &s1, &cs1);
                float y00 = x00 * cs0 - x01 * s0, y01 = x00 * s0 + x01 * cs0;
                float y10 = x10 * cs1 - x11 * s1, y11 = x10 * s1 + x11 * cs1;
                int g16 = colgrp & ~15;
                int pos = 4 * c + 2 * (nt & 1);
                *(__half2*)(C + (size_t)r0 * D_MOD + g16 + pos) = __floats2half2_rn(y00, y01);
                *(__half2*)(C + (size_t)r1 * D_MOD + g16 + pos) = __floats2half2_rn(y10, y11);
            }
        } else {
            // V transpose: g_VT[((b*16+h)*64 + d)*2048 + s_perm16]
            __half* C = (__half*)Cv;
            int bb = r0 >> 11;
            int s  = r0 & 2047;
            int sq = (s & ~15) + p16(s & 15);   // r1 -> sq + 2
            #pragma unroll
            for (int nt = 0; nt < 4; nt++) {
                int n = n0 + wn * 32 + nt * 8 + 2 * c;
                int h = n >> 6, d = n & 63;
                size_t base = ((size_t)((bb << 4) | h) * 64 + d) * 2048;
                C[base        + sq    ] = __float2half_rn(acc[mt][nt][0]);
                C[base + 2048 + sq    ] = __float2half_rn(acc[mt][nt][1]);   // d+1
                C[base        + sq + 2] = __float2half_rn(acc[mt][nt][2]);   // s+8
                C[base + 2048 + sq + 2] = __float2half_rn(acc[mt][nt][3]);
            }
        }
    }
}

// ============================================================================
// Fused causal flash attention, fp16 mma (m16n8k16), fp32 softmax.
// 128 threads, 64 queries/CTA, K/V^T cp.async double-buffered.
// Row stride 80 halves. grid = (32, 32).
// ============================================================================
#define KSTRH 80
#define FS_Q 0
#define FS_K 5120
#define FS_V (5120 + 2*5120)
#define FLASH_SMEM_BYTES ((5120 * 5) * 2)      // 51200

__global__ __launch_bounds__(128)
void flash_attn()
{
    extern __shared__ __align__(16) __half smf[];
    const int tid  = threadIdx.x;
    const int lane = tid & 31;
    const int warp = tid >> 5;
    const int g = lane >> 2;
    const int c = lane & 3;
    const int qt = (S_LEN / 64 - 1) - blockIdx.x;   // heavy tiles first
    const int bh = blockIdx.y;
    const int b = bh >> 4, h = bh & 15;

    const __half* Qg  = g_Q  + ((size_t)(b * S_LEN + qt * 64)) * D_MOD + h * 64;
    const __half* Kg  = g_K  + ((size_t)(b * S_LEN)) * D_MOD + h * 64;
    const __half* VTg = g_VT + ((size_t)((b * 16 + h) * 64)) * 2048;

    const int crow = tid >> 3;          // 0..15
    const int cc8  = (tid & 7) << 3;    // 0..56

    // stage 0: K/V^T (64 rows x 64 halves each)
    #pragma unroll
    for (int p = 0; p < 4; p++) {
        int row = crow + p * 16;
        cp16(&smf[FS_K + row * KSTRH + cc8], Kg  + (size_t)row * D_MOD + cc8);
        cp16(&smf[FS_V + row * KSTRH + cc8], VTg + (size_t)row * 2048 + cc8);
    }
    CP_COMMIT();

    // Q tile (unscaled; 1/8 applied to fp32 scores — exact)
    #pragma unroll
    for (int p = 0; p < 4; p++) {
        int row = crow + p * 16;
        *(uint4*)&smf[FS_Q + row * KSTRH + cc8] =
            *(const uint4*)(Qg + (size_t)row * D_MOD + cc8);
    }
    __syncthreads();

    // hoist Q fragments (16 regs); FS_Q becomes P afterwards
    const int qrow0 = warp * 16 + g;
    const int qrow1 = qrow0 + 8;
    unsigned qa[4][4];
    #pragma unroll
    for (int ks = 0; ks < 4; ks++) {
        uint2 v0 = *(const uint2*)&smf[FS_Q + qrow0 * KSTRH + ks * 16 + 4 * c];
        uint2 v1 = *(const uint2*)&smf[FS_Q + qrow1 * KSTRH + ks * 16 + 4 * c];
        qa[ks][0] = v0.x; qa[ks][1] = v1.x; qa[ks][2] = v0.y; qa[ks][3] = v1.y;
    }

    float m0f = -CUDART_INF_F, m1f = -CUDART_INF_F;
    float l0 = 0.f, l1 = 0.f;
    float o[8][4];
    #pragma unroll
    for (int dt = 0; dt < 8; dt++)
        #pragma unroll
        for (int r = 0; r < 4; r++) o[dt][r] = 0.f;

    for (int kt = 0; kt <= qt; kt++) {
        CP_WAIT0();
        __syncthreads();
        if (kt < qt) {
            int st = (kt + 1) & 1;
            #pragma unroll
            for (int p = 0; p < 4; p++) {
                int row = crow + p * 16;
                cp16(&smf[FS_K + st * 5120 + row * KSTRH + cc8],
                     Kg + (size_t)((kt + 1) * 64 + row) * D_MOD + cc8);
                cp16(&smf[FS_V + st * 5120 + row * KSTRH + cc8],
                     VTg + (size_t)row * 2048 + (kt + 1) * 64 + cc8);
            }
            CP_COMMIT();
        }
        const __half* Ks = smf + FS_K + (kt & 1) * 5120;
        const __half* Vs = smf + FS_V + (kt & 1) * 5120;

        // S = Q @ K^T (raw, scaled after)
        float sacc[8][4];
        #pragma unroll
        for (int nt = 0; nt < 8; nt++)
            #pragma unroll
            for (int r = 0; r < 4; r++) sacc[nt][r] = 0.f;

        #pragma unroll
        for (int ks = 0; ks < 4; ks++) {
            #pragma unroll
            for (int nt = 0; nt < 8; nt++) {
                uint2 vb = *(const uint2*)&Ks[(nt * 8 + g) * KSTRH + ks * 16 + 4 * c];
                mma16(sacc[nt], qa[ks][0], qa[ks][1], qa[ks][2], qa[ks][3], vb.x, vb.y);
            }
        }
        #pragma unroll
        for (int nt = 0; nt < 8; nt++) {
            sacc[nt][0] *= 0.125f; sacc[nt][1] *= 0.125f;
            sacc[nt][2] *= 0.125f; sacc[nt][3] *= 0.125f;
        }

        if (kt == qt) {
            #pragma unroll
            for (int nt = 0; nt < 8; nt++) {
                int k0c = nt * 8 + c * 2, k1c = k0c + 1;
                if (k0c > qrow0) sacc[nt][0] = -CUDART_INF_F;
                if (k1c > qrow0) sacc[nt][1] = -CUDART_INF_F;
                if (k0c > qrow1) sacc[nt][2] = -CUDART_INF_F;
                if (k1c > qrow1) sacc[nt][3] = -CUDART_INF_F;
            }
        }

        float r0 = -CUDART_INF_F, r1 = -CUDART_INF_F;
        #pragma unroll
        for (int nt = 0; nt < 8; nt++) {
            r0 = fmaxf(r0, fmaxf(sacc[nt][0], sacc[nt][1]));
            r1 = fmaxf(r1, fmaxf(sacc[nt][2], sacc[nt][3]));
        }
        r0 = fmaxf(r0, __shfl_xor_sync(0xffffffffu, r0, 1));
        r0 = fmaxf(r0, __shfl_xor_sync(0xffffffffu, r0, 2));
        r1 = fmaxf(r1, __shfl_xor_sync(0xffffffffu, r1, 1));
        r1 = fmaxf(r1, __shfl_xor_sync(0xffffffffu, r1, 2));
        float mn0 = fmaxf(m0f, r0), mn1 = fmaxf(m1f, r1);
        float al0 = __expf(m0f - mn0), al1 = __expf(m1f - mn1);
        m0f = mn0; m1f = mn1;

        float rs0 = 0.f, rs1 = 0.f;
        #pragma unroll
        for (int nt = 0; nt < 8; nt++) {
            float p00 = __expf(sacc[nt][0] - mn0);
            float p01 = __expf(sacc[nt][1] - mn0);
            float p10 = __expf(sacc[nt][2] - mn1);
            float p11 = __expf(sacc[nt][3] - mn1);
            rs0 += p00 + p01; rs1 += p10 + p11;
            // P -> half, stored at perm16 key positions
            int pos = (nt >> 1) * 16 + 4 * c + 2 * (nt & 1);
            *(__half2*)&smf[FS_Q + qrow0 * KSTRH + pos] = __floats2half2_rn(p00, p01);
            *(__half2*)&smf[FS_Q + qrow1 * KSTRH + pos] = __floats2half2_rn(p10, p11);
        }
        l0 = l0 * al0 + rs0;
        l1 = l1 * al1 + rs1;
        #pragma unroll
        for (int dt = 0; dt < 8; dt++) {
            o[dt][0] *= al0; o[dt][1] *= al0;
            o[dt][2] *= al1; o[dt][3] *= al1;
        }
        __syncwarp();

        // O += P @ V  (k-dim = 64 keys, 4 k16 steps)
        #pragma unroll
        for (int ks = 0; ks < 4; ks++) {
            uint2 pa0 = *(const uint2*)&smf[FS_Q + qrow0 * KSTRH + ks * 16 + 4 * c];
            uint2 pa1 = *(const uint2*)&smf[FS_Q + qrow1 * KSTRH + ks * 16 + 4 * c];
            #pragma unroll
            for (int dt = 0; dt < 8; dt++) {
                uint2 vb = *(const uint2*)&Vs[(dt * 8 + g) * KSTRH + ks * 16 + 4 * c];
                mma16(o[dt], pa0.x, pa1.x, pa0.y, pa1.y, vb.x, vb.y);
            }
        }
        __syncwarp();   // P reads done before next iter's P writes
    }

    l0 += __shfl_xor_sync(0xffffffffu, l0, 1);
    l0 += __shfl_xor_sync(0xffffffffu, l0, 2);
    l1 += __shfl_xor_sync(0xffffffffu, l1, 1);
    l1 += __shfl_xor_sync(0xffffffffu, l1, 2);
    float inv0 = 1.f / l0, inv1 = 1.f / l1;

    // store perm16 along d (matches gemm A-operand expectation)
    __half* Og = g_AO + ((size_t)(b * S_LEN + qt * 64)) * D_MOD + h * 64;
    #pragma unroll
    for (int dt = 0; dt < 8; dt++) {
        int pos = (dt >> 1) * 16 + 4 * c + 2 * (dt & 1);
        *(__half2*)(Og + (size_t)qrow0 * D_MOD + pos) =
            __floats2half2_rn(o[dt][0] * inv0, o[dt][1] * inv0);
        *(__half2*)(Og + (size_t)qrow1 * D_MOD + pos) =
            __floats2half2_rn(o[dt][2] * inv1, o[dt][3] * inv1);
    }
}

// ============================================================================
extern "C" void kernel_launch(void* const* d_in, const int* in_sizes, int n_in,
                              void* d_out, int out_size)
{
    (void)in_sizes; (void)n_in; (void)out_size;
    const float* x  = (const float*)d_in[0];
    const int*   tp = (const int*)d_in[1];
    const float* wq = (const float*)d_in[2];
    const float* wk = (const float*)d_in[3];
    const float* wv = (const float*)d_in[4];
    const float* wo = (const float*)d_in[5];
    float* out = (float*)d_out;

    __half *xptr, *wqp, *wkp, *wvp, *wop, *qptr, *kptr, *vtptr, *aoptr;
    cudaGetSymbolAddress((void**)&xptr,  g_X);
    cudaGetSymbolAddress((void**)&wqp,   g_Wq);
    cudaGetSymbolAddress((void**)&wkp,   g_Wk);
    cudaGetSymbolAddress((void**)&wvp,   g_Wv);
    cudaGetSymbolAddress((void**)&wop,   g_Wo);
    cudaGetSymbolAddress((void**)&qptr,  g_Q);
    cudaGetSymbolAddress((void**)&kptr,  g_K);
    cudaGetSymbolAddress((void**)&vtptr, g_VT);
    cudaGetSymbolAddress((void**)&aoptr, g_AO);

    cudaFuncSetAttribute(gemm_f16, cudaFuncAttributeMaxDynamicSharedMemorySize,
                         GEMM_SMEM_BYTES);
    cudaFuncSetAttribute(flash_attn, cudaFuncAttributeMaxDynamicSharedMemorySize,
                         FLASH_SMEM_BYTES);

    // 0) fp32 -> fp16 + perm16 + freq table
    preround<<<2048, 256>>>(x, wq, wk, wv, wo);

    // 1) Q/K/V projections (+ fused RoPE on Q,K; V stored transposed)
    dim3 gq(D_MOD / 128, M_TOT / 128, 3);
    gemm_f16<<<gq, 256, GEMM_SMEM_BYTES>>>(xptr, wqp, wkp, wvp,
                                           qptr, kptr, vtptr, tp, 0);

    // 2) fused causal attention
    flash_attn<<<dim3(S_LEN / 64, B_SZ * NH), 128, FLASH_SMEM_BYTES>>>();

    // 3) output projection (fp32 out)
    dim3 go(D_MOD / 128, M_TOT / 128, 1);
    gemm_f16<<<go, 256, GEMM_SMEM_BYTES>>>(aoptr, wop, wop, wop,
                                           out, out, out, nullptr, 1);
}

// round 9
// speedup vs baseline: 2.3509x; 1.0409x over previous
#include <cuda_runtime.h>
#include <cuda_fp16.h>
#include <math.h>
#include <math_constants.h>

#define B_SZ   2
#define S_LEN  2048
#define D_MOD  1024
#define NH     16
#define DK     64
#define M_TOT  (B_SZ * S_LEN)   // 4096

// Scratch (allocation-free rule: __device__ globals). All fp16, k-dim stored
// in per-16 interleaved order [k0,k1,k8,k9,k2,k3,k10,k11,k4,k5,k12,k13,k6,k7,k14,k15]
// so one LDS.64 yields an m16n8k16 fragment pair (2c,2c+1 | 2c+8,2c+9).
__device__ __half g_X [M_TOT * D_MOD];
__device__ __half g_Wq[D_MOD * D_MOD];
__device__ __half g_Wk[D_MOD * D_MOD];
__device__ __half g_Wv[D_MOD * D_MOD];
__device__ __half g_Wo[D_MOD * D_MOD];
__device__ __half g_Q [M_TOT * D_MOD];
__device__ __half g_K [M_TOT * D_MOD];
__device__ __half g_VT[M_TOT * D_MOD];   // V transposed [b,h,d,s_perm]
__device__ __half g_AO[M_TOT * D_MOD];   // attention out (perm-16 along d)
__device__ float  g_freq[512];           // RoPE inv freqs per even col

__device__ __forceinline__ unsigned h2u(__half2 v) { return *(unsigned*)&v; }

__device__ __forceinline__ void mma16(float* d,
                                      unsigned a0, unsigned a1, unsigned a2, unsigned a3,
                                      unsigned b0, unsigned b1) {
    asm volatile(
        "mma.sync.aligned.m16n8k16.row.col.f32.f16.f16.f32 "
        "{%0,%1,%2,%3}, {%4,%5,%6,%7}, {%8,%9}, {%0,%1,%2,%3};\n"
        : "+f"(d[0]), "+f"(d[1]), "+f"(d[2]), "+f"(d[3])
        : "r"(a0), "r"(a1), "r"(a2), "r"(a3), "r"(b0), "r"(b1));
}

__device__ __forceinline__ void cp16(void* smem, const void* gmem) {
    unsigned s = (unsigned)__cvta_generic_to_shared(smem);
    asm volatile("cp.async.cg.shared.global [%0], [%1], 16;" :: "r"(s), "l"(gmem));
}
#define CP_COMMIT() asm volatile("cp.async.commit_group;")
#define CP_WAIT0()  asm volatile("cp.async.wait_group 0;")

// pack two f32 -> f16x2 (lo = a, hi = b)
__device__ __forceinline__ unsigned pack_h2(float a, float b) {
    unsigned u;
    asm("cvt.rn.f16x2.f32 %0, %1, %2;" : "=r"(u) : "f"(b), "f"(a));
    return u;
}
// two exponentials (base 2) in one MUFU op
__device__ __forceinline__ unsigned ex2_h2(unsigned t) {
    unsigned p;
    asm("ex2.approx.f16x2 %0, %1;" : "=r"(p) : "r"(t));
    return p;
}
__device__ __forceinline__ float ex2f(float x) {
    float r;
    asm("ex2.approx.f32 %0, %1;" : "=f"(r) : "f"(x));
    return r;
}

// position of key j (0..15) in the per-16 interleave
__device__ __forceinline__ int p16(int j) {
    return (j < 8) ? (4 * (j >> 1) + (j & 1)) : (4 * ((j - 8) >> 1) + 2 + (j & 1));
}

// ============================================================================
// Pre-round fp32 -> fp16 (rn) + per-16 k-interleave. Also fills freq table.
// ============================================================================
__global__ __launch_bounds__(256)
void preround(const float* __restrict__ x,
              const float* __restrict__ wq, const float* __restrict__ wk,
              const float* __restrict__ wv, const float* __restrict__ wo)
{
    if (blockIdx.x == 0 && threadIdx.x < 256) {
        #pragma unroll
        for (int q = 0; q < 2; q++) {
            int j = threadIdx.x + q * 256;
            g_freq[j] = (float)exp2((double)(2 * j) * (-13.287712379549449 / 1024.0));
        }
    }
    int gidx = blockIdx.x * blockDim.x + threadIdx.x;
    const float* src; __half* dst; int off;
    if (gidx < 262144) { src = x; dst = g_X; off = gidx; }
    else {
        int t = gidx - 262144; int w = t >> 16; off = t & 65535;
        src = (w == 0) ? wq : (w == 1) ? wk : (w == 2) ? wv : wo;
        dst = (w == 0) ? g_Wq : (w == 1) ? g_Wk : (w == 2) ? g_Wv : g_Wo;
    }
    const float4* s4 = (const float4*)src + (size_t)off * 4;
    float4 f0 = s4[0], f1 = s4[1], f2 = s4[2], f3 = s4[3];
    uint4 u0, u1;
    u0.x = h2u(__floats2half2_rn(f0.x, f0.y));   // 0,1
    u0.y = h2u(__floats2half2_rn(f2.x, f2.y));   // 8,9
    u0.z = h2u(__floats2half2_rn(f0.z, f0.w));   // 2,3
    u0.w = h2u(__floats2half2_rn(f2.z, f2.w));   // 10,11
    u1.x = h2u(__floats2half2_rn(f1.x, f1.y));   // 4,5
    u1.y = h2u(__floats2half2_rn(f3.x, f3.y));   // 12,13
    u1.z = h2u(__floats2half2_rn(f1.z, f1.w));   // 6,7
    u1.w = h2u(__floats2half2_rn(f3.z, f3.w));   // 14,15
    uint4* d4 = (uint4*)(dst + (size_t)off * 16);
    d4[0] = u0;
    d4[1] = u1;
}

// ============================================================================
// FP16 GEMM: C = A @ W^T. 128x128 CTA tile, K-stage 64 halves, 16 iters.
// 8 warps (2m x 4n), warp tile 64x32, m16n8k16, LDS.64 fragments.
// 2-stage cp.async. Row stride 80 halves.
// mode 0: z<2 -> RoPE+half+perm16 (Q/K); z==2 -> V transpose store.
// mode 1: plain fp32 output.
// ============================================================================
#define SROWH 80
#define GSTGH (256 * SROWH)                    // 20480 halves per stage
#define GEMM_SMEM_BYTES (2 * GSTGH * 2)        // 81920

__global__ __launch_bounds__(256, 2)
void gemm_f16(const __half* __restrict__ A,
              const __half* __restrict__ W0, const __half* __restrict__ W1,
              const __half* __restrict__ W2,
              void* __restrict__ C0v, void* __restrict__ C1v, void* __restrict__ C2v,
              const int* __restrict__ tokpos, int mode)
{
    const __half* W = W0; void* Cv = C0v;
    if (blockIdx.z == 1) { W = W1; Cv = C1v; }
    else if (blockIdx.z == 2) { W = W2; Cv = C2v; }

    extern __shared__ __align__(16) __half smh[];

    const int tid  = threadIdx.x;
    const int lane = tid & 31;
    const int warp = tid >> 5;
    const int wm = warp >> 2;   // 0..1
    const int wn = warp & 3;    // 0..3
    const int g = lane >> 2;    // 0..7
    const int c = lane & 3;     // 0..3
    const int m0 = blockIdx.y * 128;
    const int n0 = blockIdx.x * 128;

    const int crow = tid >> 3;            // 0..31
    const int cc8  = (tid & 7) << 3;      // 0..56

    float acc[4][4][4];
    #pragma unroll
    for (int i = 0; i < 4; i++)
        #pragma unroll
        for (int j = 0; j < 4; j++)
            #pragma unroll
            for (int r = 0; r < 4; r++) acc[i][j][r] = 0.f;

    {
        __half* Xs = smh;
        __half* Ws = smh + 128 * SROWH;
        #pragma unroll
        for (int p = 0; p < 4; p++) {
            int row = crow + p * 32;
            cp16(&Xs[row * SROWH + cc8], A + (size_t)(m0 + row) * D_MOD + cc8);
            cp16(&Ws[row * SROWH + cc8], W + (size_t)(n0 + row) * D_MOD + cc8);
        }
        CP_COMMIT();
    }

    const int NIT = D_MOD / 64;   // 16
    for (int it = 0; it < NIT; it++) {
        CP_WAIT0();
        __syncthreads();
        if (it + 1 < NIT) {
            int k0 = (it + 1) * 64;
            __half* Xs = smh + ((it + 1) & 1) * GSTGH;
            __half* Ws = Xs + 128 * SROWH;
            #pragma unroll
            for (int p = 0; p < 4; p++) {
                int row = crow + p * 32;
                cp16(&Xs[row * SROWH + cc8], A + (size_t)(m0 + row) * D_MOD + k0 + cc8);
                cp16(&Ws[row * SROWH + cc8], W + (size_t)(n0 + row) * D_MOD + k0 + cc8);
            }
            CP_COMMIT();
        }

        const __half* Xs = smh + (it & 1) * GSTGH;
        const __half* Ws = Xs + 128 * SROWH;

        #pragma unroll
        for (int ks = 0; ks < 4; ks++) {
            unsigned a[4][4], b[4][2];
            #pragma unroll
            for (int mt = 0; mt < 4; mt++) {
                int rb = wm * 64 + mt * 16;
                uint2 v0 = *(const uint2*)&Xs[(rb + g    ) * SROWH + ks * 16 + 4 * c];
                uint2 v1 = *(const uint2*)&Xs[(rb + g + 8) * SROWH + ks * 16 + 4 * c];
                a[mt][0] = v0.x; a[mt][1] = v1.x;
                a[mt][2] = v0.y; a[mt][3] = v1.y;
            }
            #pragma unroll
            for (int nt = 0; nt < 4; nt++) {
                uint2 vb = *(const uint2*)&Ws[(wn * 32 + nt * 8 + g) * SROWH + ks * 16 + 4 * c];
                b[nt][0] = vb.x; b[nt][1] = vb.y;
            }
            #pragma unroll
            for (int mt = 0; mt < 4; mt++)
                #pragma unroll
                for (int nt = 0; nt < 4; nt++)
                    mma16(acc[mt][nt], a[mt][0], a[mt][1], a[mt][2], a[mt][3],
                          b[nt][0], b[nt][1]);
        }
    }
    __syncthreads();

    #pragma unroll
    for (int mt = 0; mt < 4; mt++) {
        int r0 = m0 + wm * 64 + mt * 16 + g;
        int r1 = r0 + 8;
        if (mode == 1) {
            float* C = (float*)Cv;
            #pragma unroll
            for (int nt = 0; nt < 4; nt++) {
                int col = n0 + wn * 32 + nt * 8 + c * 2;
                *(float2*)(C + (size_t)r0 * D_MOD + col) = make_float2(acc[mt][nt][0], acc[mt][nt][1]);
                *(float2*)(C + (size_t)r1 * D_MOD + col) = make_float2(acc[mt][nt][2], acc[mt][nt][3]);
            }
        } else if (blockIdx.z < 2) {
            __half* C = (__half*)Cv;
            float pf0 = (float)tokpos[r0], pf1 = (float)tokpos[r1];
            #pragma unroll
            for (int nt = 0; nt < 4; nt++) {
                int colgrp = n0 + wn * 32 + nt * 8;
                float x00 = acc[mt][nt][0], x01 = acc[mt][nt][1];
                float x10 = acc[mt][nt][2], x11 = acc[mt][nt][3];
                float freq = g_freq[(colgrp >> 1) + c];
                float s0, cs0, s1, cs1;
                sincosf(pf0 * freq, &s0, &cs0);
                sincosf(pf1 * freq, &s1, &cs1);
                float y00 = x00 * cs0 - x01 * s0, y01 = x00 * s0 + x01 * cs0;
                float y10 = x10 * cs1 - x11 * s1, y11 = x10 * s1 + x11 * cs1;
                int g16 = colgrp & ~15;
                int pos = 4 * c + 2 * (nt & 1);
                *(__half2*)(C + (size_t)r0 * D_MOD + g16 + pos) = __floats2half2_rn(y00, y01);
                *(__half2*)(C + (size_t)r1 * D_MOD + g16 + pos) = __floats2half2_rn(y10, y11);
            }
        } else {
            __half* C = (__half*)Cv;
            int bb = r0 >> 11;
            int s  = r0 & 2047;
            int sq = (s & ~15) + p16(s & 15);   // r1 -> sq + 2
            #pragma unroll
            for (int nt = 0; nt < 4; nt++) {
                int n = n0 + wn * 32 + nt * 8 + 2 * c;
                int h = n >> 6, d = n & 63;
                size_t base = ((size_t)((bb << 4) | h) * 64 + d) * 2048;
                C[base        + sq    ] = __float2half_rn(acc[mt][nt][0]);
                C[base + 2048 + sq    ] = __float2half_rn(acc[mt][nt][1]);   // d+1
                C[base        + sq + 2] = __float2half_rn(acc[mt][nt][2]);   // s+8
                C[base + 2048 + sq + 2] = __float2half_rn(acc[mt][nt][3]);
            }
        }
    }
}

// ============================================================================
// Fused causal flash attention, fp16 mma (m16n8k16), log2-domain softmax with
// ex2.approx.f16x2 (2 exps / MUFU op). 128 threads, 64 queries/CTA.
// ============================================================================
#define KSTRH 80
#define FS_Q 0
#define FS_K 5120
#define FS_V (5120 + 2*5120)
#define FLASH_SMEM_BYTES ((5120 * 5) * 2)      // 51200

__global__ __launch_bounds__(128)
void flash_attn()
{
    extern __shared__ __align__(16) __half smf[];
    const int tid  = threadIdx.x;
    const int lane = tid & 31;
    const int warp = tid >> 5;
    const int g = lane >> 2;
    const int c = lane & 3;
    const int qt = (S_LEN / 64 - 1) - blockIdx.x;   // heavy tiles first
    const int bh = blockIdx.y;
    const int b = bh >> 4, h = bh & 15;

    const __half* Qg  = g_Q  + ((size_t)(b * S_LEN + qt * 64)) * D_MOD + h * 64;
    const __half* Kg  = g_K  + ((size_t)(b * S_LEN)) * D_MOD + h * 64;
    const __half* VTg = g_VT + ((size_t)((b * 16 + h) * 64)) * 2048;

    const int crow = tid >> 3;          // 0..15
    const int cc8  = (tid & 7) << 3;    // 0..56

    #pragma unroll
    for (int p = 0; p < 4; p++) {
        int row = crow + p * 16;
        cp16(&smf[FS_K + row * KSTRH + cc8], Kg  + (size_t)row * D_MOD + cc8);
        cp16(&smf[FS_V + row * KSTRH + cc8], VTg + (size_t)row * 2048 + cc8);
    }
    CP_COMMIT();

    #pragma unroll
    for (int p = 0; p < 4; p++) {
        int row = crow + p * 16;
        *(uint4*)&smf[FS_Q + row * KSTRH + cc8] =
            *(const uint4*)(Qg + (size_t)row * D_MOD + cc8);
    }
    __syncthreads();

    const int qrow0 = warp * 16 + g;
    const int qrow1 = qrow0 + 8;
    unsigned qa[4][4];
    #pragma unroll
    for (int ks = 0; ks < 4; ks++) {
        uint2 v0 = *(const uint2*)&smf[FS_Q + qrow0 * KSTRH + ks * 16 + 4 * c];
        uint2 v1 = *(const uint2*)&smf[FS_Q + qrow1 * KSTRH + ks * 16 + 4 * c];
        qa[ks][0] = v0.x; qa[ks][1] = v1.x; qa[ks][2] = v0.y; qa[ks][3] = v1.y;
    }

    // softmax state in t-units (score * 0.125 * log2(e))
    const float CSC = 0.18033688011112042f;   // log2(e)/8
    float m0f = -CUDART_INF_F, m1f = -CUDART_INF_F;
    float l0 = 0.f, l1 = 0.f;
    float o[8][4];
    #pragma unroll
    for (int dt = 0; dt < 8; dt++)
        #pragma unroll
        for (int r = 0; r < 4; r++) o[dt][r] = 0.f;

    for (int kt = 0; kt <= qt; kt++) {
        CP_WAIT0();
        __syncthreads();
        if (kt < qt) {
            int st = (kt + 1) & 1;
            #pragma unroll
            for (int p = 0; p < 4; p++) {
                int row = crow + p * 16;
                cp16(&smf[FS_K + st * 5120 + row * KSTRH + cc8],
                     Kg + (size_t)((kt + 1) * 64 + row) * D_MOD + cc8);
                cp16(&smf[FS_V + st * 5120 + row * KSTRH + cc8],
                     VTg + (size_t)row * 2048 + (kt + 1) * 64 + cc8);
            }
            CP_COMMIT();
        }
        const __half* Ks = smf + FS_K + (kt & 1) * 5120;
        const __half* Vs = smf + FS_V + (kt & 1) * 5120;

        // S = Q @ K^T (raw scores)
        float sacc[8][4];
        #pragma unroll
        for (int nt = 0; nt < 8; nt++)
            #pragma unroll
            for (int r = 0; r < 4; r++) sacc[nt][r] = 0.f;

        #pragma unroll
        for (int ks = 0; ks < 4; ks++) {
            #pragma unroll
            for (int nt = 0; nt < 8; nt++) {
                uint2 vb = *(const uint2*)&Ks[(nt * 8 + g) * KSTRH + ks * 16 + 4 * c];
                mma16(sacc[nt], qa[ks][0], qa[ks][1], qa[ks][2], qa[ks][3], vb.x, vb.y);
            }
        }

        if (kt == qt) {
            #pragma unroll
            for (int nt = 0; nt < 8; nt++) {
                int k0c = nt * 8 + c * 2, k1c = k0c + 1;
                if (k0c > qrow0) sacc[nt][0] = -CUDART_INF_F;
                if (k1c > qrow0) sacc[nt][1] = -CUDART_INF_F;
                if (k0c > qrow1) sacc[nt][2] = -CUDART_INF_F;
                if (k1c > qrow1) sacc[nt][3] = -CUDART_INF_F;
            }
        }

        // row max over raw scores
        float r0 = -CUDART_INF_F, r1 = -CUDART_INF_F;
        #pragma unroll
        for (int nt = 0; nt < 8; nt++) {
            r0 = fmaxf(r0, fmaxf(sacc[nt][0], sacc[nt][1]));
            r1 = fmaxf(r1, fmaxf(sacc[nt][2], sacc[nt][3]));
        }
        r0 = fmaxf(r0, __shfl_xor_sync(0xffffffffu, r0, 1));
        r0 = fmaxf(r0, __shfl_xor_sync(0xffffffffu, r0, 2));
        r1 = fmaxf(r1, __shfl_xor_sync(0xffffffffu, r1, 1));
        r1 = fmaxf(r1, __shfl_xor_sync(0xffffffffu, r1, 2));
        float mn0 = fmaxf(m0f, r0 * CSC), mn1 = fmaxf(m1f, r1 * CSC);
        float al0 = ex2f(m0f - mn0), al1 = ex2f(m1f - mn1);
        m0f = mn0; m1f = mn1;

        float rs0 = 0.f, rs1 = 0.f;
        #pragma unroll
        for (int nt = 0; nt < 8; nt++) {
            float t00 = fmaf(sacc[nt][0], CSC, -mn0);
            float t01 = fmaf(sacc[nt][1], CSC, -mn0);
            float t10 = fmaf(sacc[nt][2], CSC, -mn1);
            float t11 = fmaf(sacc[nt][3], CSC, -mn1);
            unsigned p0 = ex2_h2(pack_h2(t00, t01));   // 2 exps, 1 MUFU
            unsigned p1 = ex2_h2(pack_h2(t10, t11));
            int pos = (nt >> 1) * 16 + 4 * c + 2 * (nt & 1);
            *(unsigned*)&smf[FS_Q + qrow0 * KSTRH + pos] = p0;
            *(unsigned*)&smf[FS_Q + qrow1 * KSTRH + pos] = p1;
            float2 f0 = __half22float2(*(__half2*)&p0);
            float2 f1 = __half22float2(*(__half2*)&p1);
            rs0 += f0.x + f0.y;
            rs1 += f1.x + f1.y;
        }
        l0 = l0 * al0 + rs0;
        l1 = l1 * al1 + rs1;
        #pragma unroll
        for (int dt = 0; dt < 8; dt++) {
            o[dt][0] *= al0; o[dt][1] *= al0;
            o[dt][2] *= al1; o[dt][3] *= al1;
        }
        __syncwarp();

        // O += P @ V
        #pragma unroll
        for (int ks = 0; ks < 4; ks++) {
            uint2 pa0 = *(const uint2*)&smf[FS_Q + qrow0 * KSTRH + ks * 16 + 4 * c];
            uint2 pa1 = *(const uint2*)&smf[FS_Q + qrow1 * KSTRH + ks * 16 + 4 * c];
            #pragma unroll
            for (int dt = 0; dt < 8; dt++) {
                uint2 vb = *(const uint2*)&Vs[(dt * 8 + g) * KSTRH + ks * 16 + 4 * c];
                mma16(o[dt], pa0.x, pa1.x, pa0.y, pa1.y, vb.x, vb.y);
            }
        }
        __syncwarp();
    }

    l0 += __shfl_xor_sync(0xffffffffu, l0, 1);
    l0 += __shfl_xor_sync(0xffffffffu, l0, 2);
    l1 += __shfl_xor_sync(0xffffffffu, l1, 1);
    l1 += __shfl_xor_sync(0xffffffffu, l1, 2);
    float inv0 = 1.f / l0, inv1 = 1.f / l1;

    __half* Og = g_AO + ((size_t)(b * S_LEN + qt * 64)) * D_MOD + h * 64;
    #pragma unroll
    for (int dt = 0; dt < 8; dt++) {
        int pos = (dt >> 1) * 16 + 4 * c + 2 * (dt & 1);
        *(__half2*)(Og + (size_t)qrow0 * D_MOD + pos) =
            __floats2half2_rn(o[dt][0] * inv0, o[dt][1] * inv0);
        *(__half2*)(Og + (size_t)qrow1 * D_MOD + pos) =
            __floats2half2_rn(o[dt][2] * inv1, o[dt][3] * inv1);
    }
}

// ============================================================================
extern "C" void kernel_launch(void* const* d_in, const int* in_sizes, int n_in,
                              void* d_out, int out_size)
{
    (void)in_sizes; (void)n_in; (void)out_size;
    const float* x  = (const float*)d_in[0];
    const int*   tp = (const int*)d_in[1];
    const float* wq = (const float*)d_in[2];
    const float* wk = (const float*)d_in[3];
    const float* wv = (const float*)d_in[4];
    const float* wo = (const float*)d_in[5];
    float* out = (float*)d_out;

    __half *xptr, *wqp, *wkp, *wvp, *wop, *qptr, *kptr, *vtptr, *aoptr;
    cudaGetSymbolAddress((void**)&xptr,  g_X);
    cudaGetSymbolAddress((void**)&wqp,   g_Wq);
    cudaGetSymbolAddress((void**)&wkp,   g_Wk);
    cudaGetSymbolAddress((void**)&wvp,   g_Wv);
    cudaGetSymbolAddress((void**)&wop,   g_Wo);
    cudaGetSymbolAddress((void**)&qptr,  g_Q);
    cudaGetSymbolAddress((void**)&kptr,  g_K);
    cudaGetSymbolAddress((void**)&vtptr, g_VT);
    cudaGetSymbolAddress((void**)&aoptr, g_AO);

    cudaFuncSetAttribute(gemm_f16, cudaFuncAttributeMaxDynamicSharedMemorySize,
                         GEMM_SMEM_BYTES);
    cudaFuncSetAttribute(flash_attn, cudaFuncAttributeMaxDynamicSharedMemorySize,
                         FLASH_SMEM_BYTES);

    // 0) fp32 -> fp16 + perm16 + freq table
    preround<<<2048, 256>>>(x, wq, wk, wv, wo);

    // 1) Q/K/V projections (+ fused RoPE on Q,K; V stored transposed)
    dim3 gq(D_MOD / 128, M_TOT / 128, 3);
    gemm_f16<<<gq, 256, GEMM_SMEM_BYTES>>>(xptr, wqp, wkp, wvp,
                                           qptr, kptr, vtptr, tp, 0);

    // 2) fused causal attention
    flash_attn<<<dim3(S_LEN / 64, B_SZ * NH), 128, FLASH_SMEM_BYTES>>>();

    // 3) output projection (fp32 out)
    dim3 go(D_MOD / 128, M_TOT / 128, 1);
    gemm_f16<<<go, 256, GEMM_SMEM_BYTES>>>(aoptr, wop, wop, wop,
                                           out, out, out, nullptr, 1);
}

// round 10
// speedup vs baseline: 2.3740x; 1.0098x over previous
#include <cuda_runtime.h>
#include <cuda_fp16.h>
#include <math.h>
#include <math_constants.h>

#define B_SZ   2
#define S_LEN  2048
#define D_MOD  1024
#define NH     16
#define DK     64
#define M_TOT  (B_SZ * S_LEN)   // 4096

// Scratch (allocation-free rule: __device__ globals). All fp16, NATURAL k-order
// (ldmatrix performs the fragment distribution).
__device__ __half g_X [M_TOT * D_MOD];
__device__ __half g_Wq[D_MOD * D_MOD];
__device__ __half g_Wk[D_MOD * D_MOD];
__device__ __half g_Wv[D_MOD * D_MOD];
__device__ __half g_Wo[D_MOD * D_MOD];
__device__ __half g_Q [M_TOT * D_MOD];
__device__ __half g_K [M_TOT * D_MOD];
__device__ __half g_VT[M_TOT * D_MOD];   // V transposed [b,h,d,s]
__device__ __half g_AO[M_TOT * D_MOD];   // attention out
__device__ float  g_freq[512];           // RoPE inv freqs per even col

__device__ __forceinline__ unsigned h2u(__half2 v) { return *(unsigned*)&v; }

__device__ __forceinline__ void mma16(float* d,
                                      unsigned a0, unsigned a1, unsigned a2, unsigned a3,
                                      unsigned b0, unsigned b1) {
    asm volatile(
        "mma.sync.aligned.m16n8k16.row.col.f32.f16.f16.f32 "
        "{%0,%1,%2,%3}, {%4,%5,%6,%7}, {%8,%9}, {%0,%1,%2,%3};\n"
        : "+f"(d[0]), "+f"(d[1]), "+f"(d[2]), "+f"(d[3])
        : "r"(a0), "r"(a1), "r"(a2), "r"(a3), "r"(b0), "r"(b1));
}

__device__ __forceinline__ void ldsm4(unsigned& r0, unsigned& r1,
                                      unsigned& r2, unsigned& r3, unsigned addr) {
    asm volatile("ldmatrix.sync.aligned.m8n8.x4.shared.b16 {%0,%1,%2,%3}, [%4];"
                 : "=r"(r0), "=r"(r1), "=r"(r2), "=r"(r3) : "r"(addr));
}

__device__ __forceinline__ void cp16(void* smem, const void* gmem) {
    unsigned s = (unsigned)__cvta_generic_to_shared(smem);
    asm volatile("cp.async.cg.shared.global [%0], [%1], 16;" :: "r"(s), "l"(gmem));
}
#define CP_COMMIT() asm volatile("cp.async.commit_group;")
#define CP_WAIT0()  asm volatile("cp.async.wait_group 0;")

__device__ __forceinline__ unsigned s2u(const void* p) {
    unsigned a;
    asm("{ .reg .u64 t; cvta.to.shared.u64 t, %1; cvt.u32.u64 %0, t; }" : "=r"(a) : "l"(p));
    return a;
}

// pack two f32 -> f16x2 (lo = a, hi = b)
__device__ __forceinline__ unsigned pack_h2(float a, float b) {
    unsigned u;
    asm("cvt.rn.f16x2.f32 %0, %1, %2;" : "=r"(u) : "f"(b), "f"(a));
    return u;
}
__device__ __forceinline__ unsigned ex2_h2(unsigned t) {
    unsigned p;
    asm("ex2.approx.f16x2 %0, %1;" : "=r"(p) : "r"(t));
    return p;
}
__device__ __forceinline__ float ex2f(float x) {
    float r;
    asm("ex2.approx.f32 %0, %1;" : "=f"(r) : "f"(x));
    return r;
}

// ============================================================================
// Pre-round fp32 -> fp16 (rn), natural order. Also fills freq table.
// ============================================================================
__global__ __launch_bounds__(256)
void preround(const float* __restrict__ x,
              const float* __restrict__ wq, const float* __restrict__ wk,
              const float* __restrict__ wv, const float* __restrict__ wo)
{
    if (blockIdx.x == 0 && threadIdx.x < 256) {
        #pragma unroll
        for (int q = 0; q < 2; q++) {
            int j = threadIdx.x + q * 256;
            g_freq[j] = (float)exp2((double)(2 * j) * (-13.287712379549449 / 1024.0));
        }
    }
    int gidx = blockIdx.x * blockDim.x + threadIdx.x;   // 16-float group
    const float* src; __half* dst; int off;
    if (gidx < 262144) { src = x; dst = g_X; off = gidx; }
    else {
        int t = gidx - 262144; int w = t >> 16; off = t & 65535;
        src = (w == 0) ? wq : (w == 1) ? wk : (w == 2) ? wv : wo;
        dst = (w == 0) ? g_Wq : (w == 1) ? g_Wk : (w == 2) ? g_Wv : g_Wo;
    }
    const float4* s4 = (const float4*)src + (size_t)off * 4;
    float4 f0 = s4[0], f1 = s4[1], f2 = s4[2], f3 = s4[3];
    uint4 u0, u1;
    u0.x = h2u(__floats2half2_rn(f0.x, f0.y));
    u0.y = h2u(__floats2half2_rn(f0.z, f0.w));
    u0.z = h2u(__floats2half2_rn(f1.x, f1.y));
    u0.w = h2u(__floats2half2_rn(f1.z, f1.w));
    u1.x = h2u(__floats2half2_rn(f2.x, f2.y));
    u1.y = h2u(__floats2half2_rn(f2.z, f2.w));
    u1.z = h2u(__floats2half2_rn(f3.x, f3.y));
    u1.w = h2u(__floats2half2_rn(f3.z, f3.w));
    uint4* d4 = (uint4*)(dst + (size_t)off * 16);
    d4[0] = u0;
    d4[1] = u1;
}

// ============================================================================
// FP16 GEMM: C = A @ W^T. 128x128 CTA tile, K-stage 64 halves, 16 iters.
// 8 warps (2m x 4n), warp tile 64x32, m16n8k16, ldmatrix fragment loads.
// Row stride 72 halves (144B) -> conflict-free LDSM. 2-stage cp.async.
// mode 0: z<2 -> RoPE (Q/K); z==2 -> V transpose store. mode 1: fp32 out.
// ============================================================================
#define SROWH 72
#define GSTGH (256 * SROWH)                    // 18432 halves per stage
#define GEMM_SMEM_BYTES (2 * GSTGH * 2)        // 73728

__global__ __launch_bounds__(256, 2)
void gemm_f16(const __half* __restrict__ A,
              const __half* __restrict__ W0, const __half* __restrict__ W1,
              const __half* __restrict__ W2,
              void* __restrict__ C0v, void* __restrict__ C1v, void* __restrict__ C2v,
              const int* __restrict__ tokpos, int mode)
{
    const __half* W = W0; void* Cv = C0v;
    if (blockIdx.z == 1) { W = W1; Cv = C1v; }
    else if (blockIdx.z == 2) { W = W2; Cv = C2v; }

    extern __shared__ __align__(16) __half smh[];
    const unsigned sbase = s2u(smh);

    const int tid  = threadIdx.x;
    const int lane = tid & 31;
    const int warp = tid >> 5;
    const int wm = warp >> 2;   // 0..1
    const int wn = warp & 3;    // 0..3
    const int g = lane >> 2;    // 0..7
    const int c = lane & 3;     // 0..3
    const int m0 = blockIdx.y * 128;
    const int n0 = blockIdx.x * 128;

    const int crow = tid >> 3;            // 0..31
    const int cc8  = (tid & 7) << 3;      // 0..56 (halves)

    // ldmatrix per-lane offsets (bytes)
    const unsigned aOff = (unsigned)((lane & 15) * 144 + (lane >> 4) * 16);
    const unsigned bOff = (unsigned)(((lane & 7) + ((lane >> 4) << 3)) * 144
                                     + ((lane >> 3) & 1) * 16);

    float acc[4][4][4];
    #pragma unroll
    for (int i = 0; i < 4; i++)
        #pragma unroll
        for (int j = 0; j < 4; j++)
            #pragma unroll
            for (int r = 0; r < 4; r++) acc[i][j][r] = 0.f;

    {
        __half* Xs = smh;
        __half* Ws = smh + 128 * SROWH;
        #pragma unroll
        for (int p = 0; p < 4; p++) {
            int row = crow + p * 32;
            cp16(&Xs[row * SROWH + cc8], A + (size_t)(m0 + row) * D_MOD + cc8);
            cp16(&Ws[row * SROWH + cc8], W + (size_t)(n0 + row) * D_MOD + cc8);
        }
        CP_COMMIT();
    }

    const int NIT = D_MOD / 64;   // 16
    for (int it = 0; it < NIT; it++) {
        CP_WAIT0();
        __syncthreads();
        if (it + 1 < NIT) {
            int k0 = (it + 1) * 64;
            __half* Xs = smh + ((it + 1) & 1) * GSTGH;
            __half* Ws = Xs + 128 * SROWH;
            #pragma unroll
            for (int p = 0; p < 4; p++) {
                int row = crow + p * 32;
                cp16(&Xs[row * SROWH + cc8], A + (size_t)(m0 + row) * D_MOD + k0 + cc8);
                cp16(&Ws[row * SROWH + cc8], W + (size_t)(n0 + row) * D_MOD + k0 + cc8);
            }
            CP_COMMIT();
        }

        const unsigned sA = sbase + (it & 1) * (GSTGH * 2);
        const unsigned sB = sA + 128 * 144;

        #pragma unroll
        for (int ks = 0; ks < 4; ks++) {
            unsigned a[4][4], b[2][4];
            #pragma unroll
            for (int mt = 0; mt < 4; mt++)
                ldsm4(a[mt][0], a[mt][1], a[mt][2], a[mt][3],
                      sA + (wm * 64 + mt * 16) * 144 + ks * 32 + aOff);
            #pragma unroll
            for (int np = 0; np < 2; np++)
                ldsm4(b[np][0], b[np][1], b[np][2], b[np][3],
                      sB + (wn * 32 + np * 16) * 144 + ks * 32 + bOff);
            #pragma unroll
            for (int mt = 0; mt < 4; mt++) {
                mma16(acc[mt][0], a[mt][0], a[mt][1], a[mt][2], a[mt][3], b[0][0], b[0][1]);
                mma16(acc[mt][1], a[mt][0], a[mt][1], a[mt][2], a[mt][3], b[0][2], b[0][3]);
                mma16(acc[mt][2], a[mt][0], a[mt][1], a[mt][2], a[mt][3], b[1][0], b[1][1]);
                mma16(acc[mt][3], a[mt][0], a[mt][1], a[mt][2], a[mt][3], b[1][2], b[1][3]);
            }
        }
    }
    __syncthreads();

    #pragma unroll
    for (int mt = 0; mt < 4; mt++) {
        int r0 = m0 + wm * 64 + mt * 16 + g;
        int r1 = r0 + 8;
        if (mode == 1) {
            float* C = (float*)Cv;
            #pragma unroll
            for (int nt = 0; nt < 4; nt++) {
                int col = n0 + wn * 32 + nt * 8 + c * 2;
                *(float2*)(C + (size_t)r0 * D_MOD + col) = make_float2(acc[mt][nt][0], acc[mt][nt][1]);
                *(float2*)(C + (size_t)r1 * D_MOD + col) = make_float2(acc[mt][nt][2], acc[mt][nt][3]);
            }
        } else if (blockIdx.z < 2) {
            // Q/K: RoPE on natural adjacent pairs -> half2 store
            __half* C = (__half*)Cv;
            float pf0 = (float)tokpos[r0], pf1 = (float)tokpos[r1];
            #pragma unroll
            for (int nt = 0; nt < 4; nt++) {
                int col = n0 + wn * 32 + nt * 8 + 2 * c;
                float x00 = acc[mt][nt][0], x01 = acc[mt][nt][1];
                float x10 = acc[mt][nt][2], x11 = acc[mt][nt][3];
                float freq = g_freq[col >> 1];
                float s0, cs0, s1, cs1;
                sincosf(pf0 * freq, &s0, &cs0);
                sincosf(pf1 * freq, &s1, &cs1);
                float y00 = x00 * cs0 - x01 * s0, y01 = x00 * s0 + x01 * cs0;
                float y10 = x10 * cs1 - x11 * s1, y11 = x10 * s1 + x11 * cs1;
                *(__half2*)(C + (size_t)r0 * D_MOD + col) = __floats2half2_rn(y00, y01);
                *(__half2*)(C + (size_t)r1 * D_MOD + col) = __floats2half2_rn(y10, y11);
            }
        } else {
            // V transpose: g_VT[((b*16+h)*64 + d)*2048 + s], natural both dims
            __half* C = (__half*)Cv;
            int bb = r0 >> 11;
            int s  = r0 & 2047;
            #pragma unroll
            for (int nt = 0; nt < 4; nt++) {
                int n = n0 + wn * 32 + nt * 8 + 2 * c;
                int h = n >> 6, d = n & 63;
                size_t base = ((size_t)((bb << 4) | h) * 64 + d) * 2048;
                C[base        + s    ] = __float2half_rn(acc[mt][nt][0]);
                C[base + 2048 + s    ] = __float2half_rn(acc[mt][nt][1]);   // d+1
                C[base        + s + 8] = __float2half_rn(acc[mt][nt][2]);   // s+8
                C[base + 2048 + s + 8] = __float2half_rn(acc[mt][nt][3]);
            }
        }
    }
}

// ============================================================================
// Fused causal flash attention, fp16 mma + ldmatrix, log2-domain ex2.f16x2
// softmax. 128 threads, 64 queries/CTA, natural layouts, stride 72 halves.
// ============================================================================
#define KSTRH 72
#define TILEH (64 * KSTRH)                     // 4608 halves / tile
#define QB 0
#define KB (TILEH * 2)                         // bytes: 9216
#define VB (TILEH * 6)                         // bytes: 27648
#define FLASH_SMEM_BYTES (TILEH * 10)          // 46080

__global__ __launch_bounds__(128)
void flash_attn()
{
    extern __shared__ __align__(16) __half smf[];
    const unsigned sbase = s2u(smf);
    const int tid  = threadIdx.x;
    const int lane = tid & 31;
    const int warp = tid >> 5;
    const int g = lane >> 2;
    const int c = lane & 3;
    const int qt = (S_LEN / 64 - 1) - blockIdx.x;   // heavy tiles first
    const int bh = blockIdx.y;
    const int b = bh >> 4, h = bh & 15;

    const __half* Qg  = g_Q  + ((size_t)(b * S_LEN + qt * 64)) * D_MOD + h * 64;
    const __half* Kg  = g_K  + ((size_t)(b * S_LEN)) * D_MOD + h * 64;
    const __half* VTg = g_VT + ((size_t)((b * 16 + h) * 64)) * 2048;

    const int crow = tid >> 3;          // 0..15
    const int cc8  = (tid & 7) << 3;    // 0..56

    const unsigned aOff = (unsigned)((lane & 15) * 144 + (lane >> 4) * 16);
    const unsigned bOff = (unsigned)(((lane & 7) + ((lane >> 4) << 3)) * 144
                                     + ((lane >> 3) & 1) * 16);

    #pragma unroll
    for (int p = 0; p < 4; p++) {
        int row = crow + p * 16;
        cp16(&smf[KB / 2 + row * KSTRH + cc8], Kg  + (size_t)row * D_MOD + cc8);
        cp16(&smf[VB / 2 + row * KSTRH + cc8], VTg + (size_t)row * 2048 + cc8);
    }
    CP_COMMIT();

    // Q tile (unscaled; scale folded into softmax constant)
    #pragma unroll
    for (int p = 0; p < 4; p++) {
        int row = crow + p * 16;
        *(uint4*)&smf[QB + row * KSTRH + cc8] =
            *(const uint4*)(Qg + (size_t)row * D_MOD + cc8);
    }
    __syncthreads();

    // hoist Q fragments via ldmatrix; Q tile becomes P afterwards
    const int qrow0 = warp * 16 + g;
    const int qrow1 = qrow0 + 8;
    unsigned qa[4][4];
    #pragma unroll
    for (int ks = 0; ks < 4; ks++)
        ldsm4(qa[ks][0], qa[ks][1], qa[ks][2], qa[ks][3],
              sbase + (warp * 16) * 144 + ks * 32 + aOff);

    const float CSC = 0.18033688011112042f;   // log2(e)/8
    float m0f = -CUDART_INF_F, m1f = -CUDART_INF_F;
    float l0 = 0.f, l1 = 0.f;
    float o[8][4];
    #pragma unroll
    for (int dt = 0; dt < 8; dt++)
        #pragma unroll
        for (int r = 0; r < 4; r++) o[dt][r] = 0.f;

    for (int kt = 0; kt <= qt; kt++) {
        CP_WAIT0();
        __syncthreads();
        if (kt < qt) {
            int st = (kt + 1) & 1;
            #pragma unroll
            for (int p = 0; p < 4; p++) {
                int row = crow + p * 16;
                cp16(&smf[KB / 2 + st * TILEH + row * KSTRH + cc8],
                     Kg + (size_t)((kt + 1) * 64 + row) * D_MOD + cc8);
                cp16(&smf[VB / 2 + st * TILEH + row * KSTRH + cc8],
                     VTg + (size_t)row * 2048 + (kt + 1) * 64 + cc8);
            }
            CP_COMMIT();
        }
        const unsigned sK = sbase + KB + (kt & 1) * (TILEH * 2);
        const unsigned sV = sbase + VB + (kt & 1) * (TILEH * 2);

        // S = Q @ K^T (raw scores)
        float sacc[8][4];
        #pragma unroll
        for (int nt = 0; nt < 8; nt++)
            #pragma unroll
            for (int r = 0; r < 4; r++) sacc[nt][r] = 0.f;

        #pragma unroll
        for (int ks = 0; ks < 4; ks++) {
            #pragma unroll
            for (int np = 0; np < 4; np++) {
                unsigned b0, b1, b2, b3;
                ldsm4(b0, b1, b2, b3, sK + (np * 16) * 144 + ks * 32 + bOff);
                mma16(sacc[np * 2],     qa[ks][0], qa[ks][1], qa[ks][2], qa[ks][3], b0, b1);
                mma16(sacc[np * 2 + 1], qa[ks][0], qa[ks][1], qa[ks][2], qa[ks][3], b2, b3);
            }
        }

        if (kt == qt) {
            #pragma unroll
            for (int nt = 0; nt < 8; nt++) {
                int k0c = nt * 8 + c * 2, k1c = k0c + 1;
                if (k0c > qrow0) sacc[nt][0] = -CUDART_INF_F;
                if (k1c > qrow0) sacc[nt][1] = -CUDART_INF_F;
                if (k0c > qrow1) sacc[nt][2] = -CUDART_INF_F;
                if (k1c > qrow1) sacc[nt][3] = -CUDART_INF_F;
            }
        }

        float r0 = -CUDART_INF_F, r1 = -CUDART_INF_F;
        #pragma unroll
        for (int nt = 0; nt < 8; nt++) {
            r0 = fmaxf(r0, fmaxf(sacc[nt][0], sacc[nt][1]));
            r1 = fmaxf(r1, fmaxf(sacc[nt][2], sacc[nt][3]));
        }
        r0 = fmaxf(r0, __shfl_xor_sync(0xffffffffu, r0, 1));
        r0 = fmaxf(r0, __shfl_xor_sync(0xffffffffu, r0, 2));
        r1 = fmaxf(r1, __shfl_xor_sync(0xffffffffu, r1, 1));
        r1 = fmaxf(r1, __shfl_xor_sync(0xffffffffu, r1, 2));
        float mn0 = fmaxf(m0f, r0 * CSC), mn1 = fmaxf(m1f, r1 * CSC);
        float al0 = ex2f(m0f - mn0), al1 = ex2f(m1f - mn1);
        m0f = mn0; m1f = mn1;

        float rs0 = 0.f, rs1 = 0.f;
        #pragma unroll
        for (int nt = 0; nt < 8; nt++) {
            float t00 = fmaf(sacc[nt][0], CSC, -mn0);
            float t01 = fmaf(sacc[nt][1], CSC, -mn0);
            float t10 = fmaf(sacc[nt][2], CSC, -mn1);
            float t11 = fmaf(sacc[nt][3], CSC, -mn1);
            unsigned p0 = ex2_h2(pack_h2(t00, t01));
            unsigned p1 = ex2_h2(pack_h2(t10, t11));
            int pos = nt * 8 + 2 * c;   // natural
            *(unsigned*)&smf[QB + qrow0 * KSTRH + pos] = p0;
            *(unsigned*)&smf[QB + qrow1 * KSTRH + pos] = p1;
            float2 f0 = __half22float2(*(__half2*)&p0);
            float2 f1 = __half22float2(*(__half2*)&p1);
            rs0 += f0.x + f0.y;
            rs1 += f1.x + f1.y;
        }
        l0 = l0 * al0 + rs0;
        l1 = l1 * al1 + rs1;
        #pragma unroll
        for (int dt = 0; dt < 8; dt++) {
            o[dt][0] *= al0; o[dt][1] *= al0;
            o[dt][2] *= al1; o[dt][3] *= al1;
        }
        __syncwarp();

        // O += P @ V
        #pragma unroll
        for (int ks = 0; ks < 4; ks++) {
            unsigned pa0, pa1, pa2, pa3;
            ldsm4(pa0, pa1, pa2, pa3, sbase + (warp * 16) * 144 + ks * 32 + aOff);
            #pragma unroll
            for (int dp = 0; dp < 4; dp++) {
                unsigned v0, v1, v2, v3;
                ldsm4(v0, v1, v2, v3, sV + (dp * 16) * 144 + ks * 32 + bOff);
                mma16(o[dp * 2],     pa0, pa1, pa2, pa3, v0, v1);
                mma16(o[dp * 2 + 1], pa0, pa1, pa2, pa3, v2, v3);
            }
        }
        __syncwarp();   // P reads done before next iter's P writes
    }

    l0 += __shfl_xor_sync(0xffffffffu, l0, 1);
    l0 += __shfl_xor_sync(0xffffffffu, l0, 2);
    l1 += __shfl_xor_sync(0xffffffffu, l1, 1);
    l1 += __shfl_xor_sync(0xffffffffu, l1, 2);
    float inv0 = 1.f / l0, inv1 = 1.f / l1;

    __half* Og = g_AO + ((size_t)(b * S_LEN + qt * 64)) * D_MOD + h * 64;
    #pragma unroll
    for (int dt = 0; dt < 8; dt++) {
        int pos = dt * 8 + 2 * c;   // natural
        *(__half2*)(Og + (size_t)qrow0 * D_MOD + pos) =
            __floats2half2_rn(o[dt][0] * inv0, o[dt][1] * inv0);
        *(__half2*)(Og + (size_t)qrow1 * D_MOD + pos) =
            __floats2half2_rn(o[dt][2] * inv1, o[dt][3] * inv1);
    }
}

// ============================================================================
extern "C" void kernel_launch(void* const* d_in, const int* in_sizes, int n_in,
                              void* d_out, int out_size)
{
    (void)in_sizes; (void)n_in; (void)out_size;
    const float* x  = (const float*)d_in[0];
    const int*   tp = (const int*)d_in[1];
    const float* wq = (const float*)d_in[2];
    const float* wk = (const float*)d_in[3];
    const float* wv = (const float*)d_in[4];
    const float* wo = (const float*)d_in[5];
    float* out = (float*)d_out;

    __half *xptr, *wqp, *wkp, *wvp, *wop, *qptr, *kptr, *vtptr, *aoptr;
    cudaGetSymbolAddress((void**)&xptr,  g_X);
    cudaGetSymbolAddress((void**)&wqp,   g_Wq);
    cudaGetSymbolAddress((void**)&wkp,   g_Wk);
    cudaGetSymbolAddress((void**)&wvp,   g_Wv);
    cudaGetSymbolAddress((void**)&wop,   g_Wo);
    cudaGetSymbolAddress((void**)&qptr,  g_Q);
    cudaGetSymbolAddress((void**)&kptr,  g_K);
    cudaGetSymbolAddress((void**)&vtptr, g_VT);
    cudaGetSymbolAddress((void**)&aoptr, g_AO);

    cudaFuncSetAttribute(gemm_f16, cudaFuncAttributeMaxDynamicSharedMemorySize,
                         GEMM_SMEM_BYTES);
    cudaFuncSetAttribute(flash_attn, cudaFuncAttributeMaxDynamicSharedMemorySize,
                         FLASH_SMEM_BYTES);

    // 0) fp32 -> fp16 + freq table
    preround<<<2048, 256>>>(x, wq, wk, wv, wo);

    // 1) Q/K/V projections (+ fused RoPE on Q,K; V stored transposed)
    dim3 gq(D_MOD / 128, M_TOT / 128, 3);
    gemm_f16<<<gq, 256, GEMM_SMEM_BYTES>>>(xptr, wqp, wkp, wvp,
                                           qptr, kptr, vtptr, tp, 0);

    // 2) fused causal attention
    flash_attn<<<dim3(S_LEN / 64, B_SZ * NH), 128, FLASH_SMEM_BYTES>>>();

    // 3) output projection (fp32 out)
    dim3 go(D_MOD / 128, M_TOT / 128, 1);
    gemm_f16<<<go, 256, GEMM_SMEM_BYTES>>>(aoptr, wop, wop, wop,
                                           out, out, out, nullptr, 1);
}